// round 15
// baseline (speedup 1.0000x reference)
#include <cuda_runtime.h>
#include <cuda_bf16.h>
#include <cstdint>

// ---------------- problem dims ----------------
#define B_   2048
#define F_   267
#define L_   32
#define H_   256
#define E_   8
#define G_   64

#define KP_ENC 576
#define KP_ZC  304
#define KP_G0  320
#define IN1_   288
#define NP_W2  320

#define SPLIT_MAX 9

#define KT_ENC 9
#define KT_G0  5
#define KT_L0 38
#define KT_L12 36
#define NT_L01 4
#define NT_L2 5
#define WTE1_SZ (4*KT_ENC*4096)
#define WTE2_SZ (4*KT_ENC*4096)
#define WTMV_SZ (1*KT_ENC*4096)
#define WG0T_SZ (1*KT_G0*4096)
#define WT0_SZ (NT_L01*KT_L0*4096)
#define WT1_SZ (NT_L01*KT_L12*4096)
#define WT2_SZ (NT_L2*KT_L12*4096)

// ---------------- device scratch ----------------
__device__ __align__(16) __nv_bfloat16 g_encAh[B_*KP_ENC];
__device__ __align__(16) __nv_bfloat16 g_encAl[B_*KP_ENC];
__device__ __align__(16) __nv_bfloat16 g_encBh[B_*KP_ENC];
__device__ __align__(16) __nv_bfloat16 g_encBl[B_*KP_ENC];
__device__ __align__(16) __nv_bfloat16 g_zch  [B_*KP_G0];
__device__ __align__(16) __nv_bfloat16 g_zcl  [B_*KP_G0];
__device__ __align__(16) float g_z    [B_*L_];
__device__ __align__(16) float g_zc   [B_*KP_ZC];
__device__ __align__(16) float g_g0o  [B_*G_];
__device__ __align__(16) float g_coef [B_*E_];
__device__ __align__(16) float g_d0   [B_*H_];
__device__ __align__(16) float g_d1   [B_*H_];
__device__ __align__(16) float g_part [SPLIT_MAX*B_*NP_W2];
__device__ __align__(16) float g_bmulv[64];
__device__ __align__(16) float g_wg1  [G_*G_];
__device__ __align__(16) __nv_bfloat16 g_wte1h[WTE1_SZ];
__device__ __align__(16) __nv_bfloat16 g_wte1l[WTE1_SZ];
__device__ __align__(16) __nv_bfloat16 g_wte2h[WTE2_SZ];
__device__ __align__(16) __nv_bfloat16 g_wte2l[WTE2_SZ];
__device__ __align__(16) __nv_bfloat16 g_wtmvh[WTMV_SZ];
__device__ __align__(16) __nv_bfloat16 g_wtmvl[WTMV_SZ];
__device__ __align__(16) __nv_bfloat16 g_wg0th[WG0T_SZ];
__device__ __align__(16) __nv_bfloat16 g_wg0tl[WG0T_SZ];
__device__ __align__(16) __nv_bfloat16 g_wt0h[WT0_SZ];
__device__ __align__(16) __nv_bfloat16 g_wt0l[WT0_SZ];
__device__ __align__(16) __nv_bfloat16 g_wt1h[WT1_SZ];
__device__ __align__(16) __nv_bfloat16 g_wt1l[WT1_SZ];
__device__ __align__(16) __nv_bfloat16 g_wt2h[WT2_SZ];
__device__ __align__(16) __nv_bfloat16 g_wt2l[WT2_SZ];

__device__ __forceinline__ float elu1(float v) { return v > 0.f ? v : expm1f(v); }
__device__ __forceinline__ void split_bf16(float v, __nv_bfloat16& h, __nv_bfloat16& l) {
    h = __float2bfloat16(v);
    l = __float2bfloat16(v - __bfloat162float(h));
}

// ---------------- mma.sync + cp.async helpers ----------------
__device__ __forceinline__ uint32_t smem_u32(const void* p) {
    uint32_t a;
    asm("{ .reg .u64 t; cvta.to.shared.u64 t, %1; cvt.u32.u64 %0, t; }" : "=r"(a) : "l"(p));
    return a;
}
__device__ __forceinline__ void ldsm_x4(uint32_t* r, uint32_t addr) {
    asm volatile("ldmatrix.sync.aligned.m8n8.x4.shared.b16 {%0,%1,%2,%3}, [%4];"
                 : "=r"(r[0]), "=r"(r[1]), "=r"(r[2]), "=r"(r[3]) : "r"(addr));
}
__device__ __forceinline__ void mma16816(float* c, const uint32_t* a, const uint32_t* b) {
    asm volatile("mma.sync.aligned.m16n8k16.row.col.f32.bf16.bf16.f32 "
                 "{%0,%1,%2,%3}, {%4,%5,%6,%7}, {%8,%9}, {%0,%1,%2,%3};"
                 : "+f"(c[0]), "+f"(c[1]), "+f"(c[2]), "+f"(c[3])
                 : "r"(a[0]), "r"(a[1]), "r"(a[2]), "r"(a[3]), "r"(b[0]), "r"(b[1]));
}
__device__ __forceinline__ void cp16(uint32_t smem_dst, const void* gsrc) {
    asm volatile("cp.async.cg.shared.global [%0], [%1], 16;" :: "r"(smem_dst), "l"(gsrc));
}
#define CP_COMMIT() asm volatile("cp.async.commit_group;" ::: "memory")
#define CP_WAIT0()  asm volatile("cp.async.wait_group 0;" ::: "memory")

// ---------------- ONE mega prep/pack kernel ----------------
// ranges: [bmulv 64][wg1 4096][tensor-weight tiles][encA][encB][zc][zch]
#define MP0 64
#define MP1 (G_*G_)
#define MPW (WTE1_SZ+WTE2_SZ+WTMV_SZ+WG0T_SZ+WT0_SZ+WT1_SZ+WT2_SZ)
#define MP2 (B_*KP_ENC)
#define MP3 (B_*320)
#define MP4 (B_*272)
#define MP5 (B_*288)
#define MPTOT (MP0+MP1+MPW+MP2+MP3+MP4+MP5)

__global__ void megaprep(const float* __restrict__ x, const float* __restrict__ c,
                         const float* __restrict__ fc1_w, const float* __restrict__ fc2_w,
                         const float* __restrict__ mu_w, const float* __restrict__ mu_b,
                         const float* __restrict__ lv_w, const float* __restrict__ lv_b,
                         const float* __restrict__ g0_w, const float* __restrict__ g1_w,
                         const float* __restrict__ w0, const float* __restrict__ w1,
                         const float* __restrict__ w2,
                         float* __restrict__ bmulv, float* __restrict__ wg1,
                         __nv_bfloat16* __restrict__ we1h, __nv_bfloat16* __restrict__ we1l,
                         __nv_bfloat16* __restrict__ we2h, __nv_bfloat16* __restrict__ we2l,
                         __nv_bfloat16* __restrict__ wmvh, __nv_bfloat16* __restrict__ wmvl,
                         __nv_bfloat16* __restrict__ wg0h, __nv_bfloat16* __restrict__ wg0l,
                         __nv_bfloat16* __restrict__ wt0h, __nv_bfloat16* __restrict__ wt0l,
                         __nv_bfloat16* __restrict__ wt1h, __nv_bfloat16* __restrict__ wt1l,
                         __nv_bfloat16* __restrict__ wt2h, __nv_bfloat16* __restrict__ wt2l,
                         __nv_bfloat16* __restrict__ eAh, __nv_bfloat16* __restrict__ eAl,
                         __nv_bfloat16* __restrict__ eBh, __nv_bfloat16* __restrict__ eBl,
                         float* __restrict__ zc,
                         __nv_bfloat16* __restrict__ zch, __nv_bfloat16* __restrict__ zcl) {
    int idx = blockIdx.x * blockDim.x + threadIdx.x;
    if (idx >= MPTOT) return;
    if (idx < MP0) {
        bmulv[idx] = (idx < 32) ? mu_b[idx] : lv_b[idx - 32];
        return;
    } idx -= MP0;
    if (idx < MP1) {
        int k = idx / G_, n = idx % G_;
        wg1[idx] = g1_w[n * G_ + k];
        return;
    } idx -= MP1;
    if (idx < MPW) {
        int layer, KT;
        __nv_bfloat16 *dh, *dl;
        int j = idx;
        if (j < WTE1_SZ) { layer = 0; KT = KT_ENC; dh = we1h; dl = we1l; }
        else if (j < WTE1_SZ + WTE2_SZ) { j -= WTE1_SZ; layer = 1; KT = KT_ENC; dh = we2h; dl = we2l; }
        else if (j < WTE1_SZ + WTE2_SZ + WTMV_SZ) { j -= WTE1_SZ + WTE2_SZ; layer = 2; KT = KT_ENC; dh = wmvh; dl = wmvl; }
        else if (j < WTE1_SZ + WTE2_SZ + WTMV_SZ + WG0T_SZ) { j -= WTE1_SZ + WTE2_SZ + WTMV_SZ; layer = 6; KT = KT_G0; dh = wg0h; dl = wg0l; }
        else if (j < WTE1_SZ + WTE2_SZ + WTMV_SZ + WG0T_SZ + WT0_SZ) { j -= WTE1_SZ + WTE2_SZ + WTMV_SZ + WG0T_SZ; layer = 3; KT = KT_L0; dh = wt0h; dl = wt0l; }
        else if (j < WTE1_SZ + WTE2_SZ + WTMV_SZ + WG0T_SZ + WT0_SZ + WT1_SZ) { j -= WTE1_SZ + WTE2_SZ + WTMV_SZ + WG0T_SZ + WT0_SZ; layer = 4; KT = KT_L12; dh = wt1h; dl = wt1l; }
        else { j -= WTE1_SZ + WTE2_SZ + WTMV_SZ + WG0T_SZ + WT0_SZ + WT1_SZ; layer = 5; KT = KT_L12; dh = wt2h; dl = wt2l; }
        int tile = j >> 12, u = j & 4095;
        int ntile = tile / KT, kt = tile % KT;
        int nrow = u >> 6, kc = u & 63;
        int n = ntile * 64 + nrow;
        int kg = kt * 64 + kc;
        float w = 0.f;
        if (layer == 0) {
            if (kg < 534) w = fc1_w[(size_t)n * 534 + kg];
        } else if (layer == 1) {
            if (kg < 523) w = fc2_w[(size_t)n * 523 + kg];
        } else if (layer == 2) {
            if (kg < 523) w = (n < 32) ? mu_w[(size_t)n * 523 + kg]
                                       : lv_w[(size_t)(n - 32) * 523 + kg];
        } else if (layer == 6) {
            if (kg < 299) w = g0_w[(size_t)n * 299 + kg];
        } else if (layer == 3) {
            int e = kg / KP_ZC, i = kg - e * KP_ZC;
            if (i < 299) w = w0[((size_t)(e * 299 + i)) * 256 + n];
        } else if (layer == 4) {
            w = w1[(size_t)kg * 256 + n];
        } else {
            if (n < 267) w = w2[(size_t)kg * 267 + n];
        }
        __nv_bfloat16 hi, lo;
        split_bf16(w, hi, lo);
        size_t dst = ((size_t)tile << 12) + u;
        dh[dst] = hi;
        dl[dst] = lo;
        return;
    } idx -= MPW;
    if (idx < MP2) {
        int b = idx / KP_ENC, k = idx % KP_ENC;
        float v = 0.f;
        if (k < 267)      v = x[b * 267 + k];
        else if (k < 534) v = c[b * 267 + (k - 267)];
        __nv_bfloat16 h, l;
        split_bf16(v, h, l);
        eAh[idx] = h;
        eAl[idx] = l;
        return;
    } idx -= MP2;
    if (idx < MP3) {
        int b = idx / 320, j = idx % 320;
        int k = (j < 267) ? j : (523 + (j - 267));
        float v = (j < 267) ? x[b * 267 + j] : 0.f;
        __nv_bfloat16 h, l;
        split_bf16(v, h, l);
        eBh[b * KP_ENC + k] = h;
        eBl[b * KP_ENC + k] = l;
        return;
    } idx -= MP3;
    if (idx < MP4) {
        int b = idx / 272, k = 32 + idx % 272;
        zc[b * KP_ZC + k] = (k < 299) ? c[b * 267 + (k - 32)] : 0.f;
        return;
    } idx -= MP4;
    {
        int b = idx / 288, k = 32 + idx % 288;
        float v = (k < 299) ? c[b * 267 + (k - 32)] : 0.f;
        __nv_bfloat16 h, l;
        split_bf16(v, h, l);
        zch[b * KP_G0 + k] = h;
        zcl[b * KP_G0 + k] = l;
    }
}

// ---------------- threefry + erfinv ----------------
__device__ __forceinline__ uint32_t rotl32(uint32_t v, int d) { return (v << d) | (v >> (32 - d)); }
__device__ __forceinline__ void tf4(uint32_t& x0, uint32_t& x1, int r0, int r1, int r2, int r3) {
    x0 += x1; x1 = rotl32(x1, r0); x1 ^= x0;
    x0 += x1; x1 = rotl32(x1, r1); x1 ^= x0;
    x0 += x1; x1 = rotl32(x1, r2); x1 ^= x0;
    x0 += x1; x1 = rotl32(x1, r3); x1 ^= x0;
}
__device__ __forceinline__ void threefry2x32(uint32_t k0, uint32_t k1, uint32_t& x0, uint32_t& x1) {
    uint32_t k2 = k0 ^ k1 ^ 0x1BD11BDAu;
    x0 += k0; x1 += k1;
    tf4(x0, x1, 13, 15, 26, 6);  x0 += k1; x1 += k2 + 1u;
    tf4(x0, x1, 17, 29, 16, 24); x0 += k2; x1 += k0 + 2u;
    tf4(x0, x1, 13, 15, 26, 6);  x0 += k0; x1 += k1 + 3u;
    tf4(x0, x1, 17, 29, 16, 24); x0 += k1; x1 += k2 + 4u;
    tf4(x0, x1, 13, 15, 26, 6);  x0 += k2; x1 += k0 + 5u;
}
__device__ __forceinline__ float erfinv_xla(float x) {
    float w = -log1pf(-x * x);
    float p;
    if (w < 5.0f) {
        w -= 2.5f;
        p = 2.81022636e-08f;
        p = fmaf(p, w, 3.43273939e-07f);
        p = fmaf(p, w, -3.5233877e-06f);
        p = fmaf(p, w, -4.39150654e-06f);
        p = fmaf(p, w, 0.00021858087f);
        p = fmaf(p, w, -0.00125372503f);
        p = fmaf(p, w, -0.00417768164f);
        p = fmaf(p, w, 0.246640727f);
        p = fmaf(p, w, 1.50140941f);
    } else {
        w = sqrtf(w) - 3.0f;
        p = -0.000200214257f;
        p = fmaf(p, w, 0.000100950558f);
        p = fmaf(p, w, 0.00134934322f);
        p = fmaf(p, w, -0.00367342844f);
        p = fmaf(p, w, 0.00573950773f);
        p = fmaf(p, w, -0.0076224613f);
        p = fmaf(p, w, 0.00943887047f);
        p = fmaf(p, w, 1.00167406f);
        p = fmaf(p, w, 2.83297682f);
    }
    return p * x;
}

__global__ void combine_zeps(const float* __restrict__ part, int S,
                             const float* __restrict__ bmulv,
                             float* __restrict__ zout, float* __restrict__ zc,
                             __nv_bfloat16* __restrict__ zch, __nv_bfloat16* __restrict__ zcl,
                             float* __restrict__ out_mu, float* __restrict__ out_lv) {
    int i = blockIdx.x * blockDim.x + threadIdx.x;
    if (i >= B_ * L_) return;
    int b = i >> 5, l = i & 31;
    float mu = bmulv[l], lv = bmulv[32 + l];
    for (int s = 0; s < S; s++) {
        const float* p = part + (size_t)s * B_ * 64 + (size_t)b * 64;
        mu += p[l];
        lv += p[32 + l];
    }
    uint32_t x0 = 0u, x1 = (uint32_t)i;
    threefry2x32(0u, 42u, x0, x1);
    uint32_t bits = x0 ^ x1;
    float f = __uint_as_float((bits >> 9) | 0x3f800000u) - 1.0f;
    const float lo = -0.99999994f;
    float u = fmaxf(lo, fmaf(f, 2.0f, lo));
    float eps = 1.41421354f * erfinv_xla(u);
    float zv = fmaf(eps, expf(0.5f * lv), mu);
    zout[i] = zv;
    zc[b * KP_ZC + l] = zv;
    __nv_bfloat16 h, l2;
    split_bf16(zv, h, l2);
    zch[b * KP_G0 + l] = h;
    zcl[b * KP_G0 + l] = l2;
    out_mu[i] = mu;
    out_lv[i] = lv;
}

// ---------------- fused gate g1 + g2 + softmax ----------------
__global__ void gate12(const float* __restrict__ g0o,
                       const float* __restrict__ wg1,
                       const float* __restrict__ g1_b,
                       const float* __restrict__ g2w,
                       const float* __restrict__ g2b,
                       float* __restrict__ coeff) {
    int gtid = blockIdx.x * blockDim.x + threadIdx.x;
    int row = gtid >> 5, lane = gtid & 31;
    if (row >= B_) return;
    float v0 = g0o[row * G_ + lane];
    float v1 = g0o[row * G_ + 32 + lane];
    float h0 = g1_b[lane], h1 = g1_b[32 + lane];
    #pragma unroll
    for (int k = 0; k < 32; k++) {
        float a0 = __shfl_sync(0xffffffffu, v0, k);
        float a1 = __shfl_sync(0xffffffffu, v1, k);
        h0 = fmaf(a0, wg1[k * G_ + lane], h0);
        h1 = fmaf(a0, wg1[k * G_ + 32 + lane], h1);
        h0 = fmaf(a1, wg1[(32 + k) * G_ + lane], h0);
        h1 = fmaf(a1, wg1[(32 + k) * G_ + 32 + lane], h1);
    }
    h0 = elu1(h0);
    h1 = elu1(h1);
    float lg[E_];
    #pragma unroll
    for (int e = 0; e < E_; e++) {
        float p = fmaf(h0, g2w[e * G_ + lane], h1 * g2w[e * G_ + 32 + lane]);
        #pragma unroll
        for (int d = 16; d > 0; d >>= 1) p += __shfl_xor_sync(0xffffffffu, p, d);
        lg[e] = p + g2b[e];
    }
    float m = lg[0];
    #pragma unroll
    for (int e = 1; e < E_; e++) m = fmaxf(m, lg[e]);
    float s = 0.f;
    #pragma unroll
    for (int e = 0; e < E_; e++) { lg[e] = expf(lg[e] - m); s += lg[e]; }
    if (lane < E_) coeff[row * E_ + lane] = lg[lane] / s;
}

// ---------------- mma.sync GEMM: BM=64, BN=64, double-buffered cp.async (R13) ----------------
#define LDS_AB 144
#define TS_A 9216
#define TS_B 9216
#define TSTAGE (2*TS_A + 2*TS_B)      // 36864
#define TSM_TOTAL (2*TSTAGE)          // 73728

template <int MODE>
__global__ void __launch_bounds__(256) tgemm(
    const float* __restrict__ src, int lda,
    const __nv_bfloat16* __restrict__ ah, const __nv_bfloat16* __restrict__ al,
    const float* __restrict__ z,
    const float* __restrict__ coeff,
    const __nv_bfloat16* __restrict__ wth,
    const __nv_bfloat16* __restrict__ wtl,
    float* __restrict__ C, int ldc, long sliceStride,
    int ktTot, int ktPer, int KT)
{
    extern __shared__ __align__(16) char smem[];
    uint32_t sb = smem_u32(smem);
    int tid = threadIdx.x;
    int wid = tid >> 5, lane = tid & 31;
    int wm = wid >> 1, wn = wid & 1;
    int m0 = blockIdx.y * 64;
    int ntile = blockIdx.x, n0 = ntile * 64;
    int kt0 = blockIdx.z * ktPer;
    int ktn = min(ktPer, ktTot - kt0);
    float* Cp = C + (long)blockIdx.z * sliceStride;

    float acc[4][4];
    #pragma unroll
    for (int nt = 0; nt < 4; nt++)
        #pragma unroll
        for (int j = 0; j < 4; j++) acc[nt][j] = 0.f;

    auto fill = [&](int kt, int buf) {
        uint32_t st = sb + buf * TSTAGE;
        if (MODE == 0) {
            #pragma unroll
            for (int gq = 0; gq < 4; gq++) {
                int g = tid + gq * 256;
                int sel = g >> 9;
                int r = (g >> 3) & 63, seg = g & 7;
                const __nv_bfloat16* srcp = (sel ? al : ah) + (size_t)(m0 + r) * lda + (kt << 6) + (seg << 3);
                cp16(st + sel * TS_A + r * LDS_AB + seg * 16, srcp);
            }
        } else {
            char* stc = smem + buf * TSTAGE;
            #pragma unroll
            for (int gq = 0; gq < 2; gq++) {
                int g = tid + gq * 256;
                int row = g >> 3, c8 = g & 7;
                int m = m0 + row;
                int kg = (kt << 6) + (c8 << 3);
                float4 f0, f1;
                float cf;
                if (MODE == 1) {
                    int e = kg / KP_ZC, i = kg - e * KP_ZC;
                    cf = coeff[m * E_ + e];
                    f0 = *(const float4*)(src + (size_t)m * KP_ZC + i);
                    f1 = *(const float4*)(src + (size_t)m * KP_ZC + i + 4);
                } else {
                    int e = kg / IN1_, i = kg - e * IN1_;
                    cf = coeff[m * E_ + e];
                    if (i < L_) {
                        f0 = *(const float4*)(z + (size_t)m * L_ + i);
                        f1 = *(const float4*)(z + (size_t)m * L_ + i + 4);
                    } else {
                        f0 = *(const float4*)(src + (size_t)m * H_ + (i - L_));
                        f1 = *(const float4*)(src + (size_t)m * H_ + (i - L_) + 4);
                    }
                }
                float v[8] = { cf * f0.x, cf * f0.y, cf * f0.z, cf * f0.w,
                               cf * f1.x, cf * f1.y, cf * f1.z, cf * f1.w };
                union { __nv_bfloat16 b[8]; uint4 u; } hv, lv;
                #pragma unroll
                for (int j = 0; j < 8; j++) split_bf16(v[j], hv.b[j], lv.b[j]);
                *(uint4*)(stc + row * LDS_AB + c8 * 16) = hv.u;
                *(uint4*)(stc + TS_A + row * LDS_AB + c8 * 16) = lv.u;
            }
        }
        const __nv_bfloat16* th = wth + ((size_t)(ntile * KT + kt) << 12);
        const __nv_bfloat16* tl = wtl + ((size_t)(ntile * KT + kt) << 12);
        #pragma unroll
        for (int gq = 0; gq < 2; gq++) {
            int g = tid + gq * 256;
            int n = g >> 3, seg = g & 7;
            cp16(st + 2 * TS_A + n * LDS_AB + seg * 16, th + n * 64 + seg * 8);
            cp16(st + 2 * TS_A + TS_B + n * LDS_AB + seg * 16, tl + n * 64 + seg * 8);
        }
    };

    fill(kt0, 0);
    CP_COMMIT();
    CP_WAIT0();
    __syncthreads();

    for (int t = 0; t < ktn; t++) {
        int buf = t & 1;
        bool more = (t + 1) < ktn;
        if (more) {
            fill(kt0 + t + 1, buf ^ 1);
            CP_COMMIT();
        }

        uint32_t sA = sb + buf * TSTAGE;
        uint32_t sB = sA + 2 * TS_A;
        int arow = wm * 16 + (lane & 15);
        int bn = wn * 32 + ((lane >> 4) << 3) + (lane & 7);
        int bkl = ((lane >> 3) & 1) << 3;
        #pragma unroll
        for (int ks = 0; ks < 4; ks++) {
            uint32_t ahf[4], alf[4];
            uint32_t bh0[4], bh1[4], bl0[4], bl1[4];
            uint32_t aAdr = sA + arow * LDS_AB + (ks * 16 + (lane >> 4) * 8) * 2;
            ldsm_x4(ahf, aAdr);
            ldsm_x4(alf, aAdr + TS_A);
            uint32_t bAdr = sB + bn * LDS_AB + (ks * 16 + bkl) * 2;
            ldsm_x4(bh0, bAdr);
            ldsm_x4(bh1, bAdr + 16 * LDS_AB);
            ldsm_x4(bl0, bAdr + TS_B);
            ldsm_x4(bl1, bAdr + TS_B + 16 * LDS_AB);

            mma16816(acc[0], ahf, bh0);     mma16816(acc[1], ahf, bh0 + 2);
            mma16816(acc[2], ahf, bh1);     mma16816(acc[3], ahf, bh1 + 2);

            mma16816(acc[0], ahf, bl0);     mma16816(acc[1], ahf, bl0 + 2);
            mma16816(acc[2], ahf, bl1);     mma16816(acc[3], ahf, bl1 + 2);

            mma16816(acc[0], alf, bh0);     mma16816(acc[1], alf, bh0 + 2);
            mma16816(acc[2], alf, bh1);     mma16816(acc[3], alf, bh1 + 2);
        }
        if (more) CP_WAIT0();
        __syncthreads();
    }

    #pragma unroll
    for (int nt = 0; nt < 4; nt++) {
        int m = m0 + wm * 16 + (lane >> 2);
        int n = n0 + wn * 32 + nt * 8 + ((lane & 3) << 1);
        *(float2*)(Cp + (size_t)m * ldc + n) = make_float2(acc[nt][0], acc[nt][1]);
        *(float2*)(Cp + (size_t)(m + 8) * ldc + n) = make_float2(acc[nt][2], acc[nt][3]);
    }
}

// ---------------- split-K combines ----------------
__global__ void combine(const float* __restrict__ part, int S, int ldp,
                        float* __restrict__ C, int ldc, int Nout,
                        const float* __restrict__ bias,
                        const float* __restrict__ coeff,
                        const float* __restrict__ ebias, int ebld,
                        int act)
{
    int idx = blockIdx.x * blockDim.x + threadIdx.x;
    if (idx >= B_ * Nout) return;
    int m = idx / Nout, n = idx % Nout;
    float v = 0.f;
    for (int s = 0; s < S; s++) v += part[(size_t)s * B_ * ldp + (size_t)m * ldp + n];
    if (bias) v += bias[n];
    if (ebias) {
        const float* cf = coeff + m * E_;
        float bm = 0.f;
        #pragma unroll
        for (int e = 0; e < E_; e++) bm = fmaf(cf[e], ebias[e * ebld + n], bm);
        v += bm;
    }
    if (act) v = elu1(v);
    C[(size_t)m * ldc + n] = v;
}

__global__ void combine_h(const float* __restrict__ part, int S,
                          __nv_bfloat16* __restrict__ Ch, __nv_bfloat16* __restrict__ Cl,
                          const float* __restrict__ bias)
{
    int idx = blockIdx.x * blockDim.x + threadIdx.x;
    if (idx >= B_ * H_) return;
    int m = idx / H_, n = idx % H_;
    float v = bias[n];
    for (int s = 0; s < S; s++) v += part[(size_t)s * B_ * 256 + (size_t)m * 256 + n];
    v = elu1(v);
    __nv_bfloat16 h, l;
    split_bf16(v, h, l);
    size_t dst = (size_t)m * KP_ENC + 267 + n;
    Ch[dst] = h;
    Cl[dst] = l;
}

// ---------------- host launch ----------------
static inline void* sym(const void* s) { void* p = nullptr; cudaGetSymbolAddress(&p, s); return p; }

extern "C" void kernel_launch(void* const* d_in, const int* in_sizes, int n_in,
                              void* d_out, int out_size) {
    (void)in_sizes; (void)n_in; (void)out_size;
    const float* x     = (const float*)d_in[0];
    const float* c     = (const float*)d_in[1];
    const float* fc1_w = (const float*)d_in[2];
    const float* fc1_b = (const float*)d_in[3];
    const float* fc2_w = (const float*)d_in[4];
    const float* fc2_b = (const float*)d_in[5];
    const float* mu_w  = (const float*)d_in[6];
    const float* mu_b  = (const float*)d_in[7];
    const float* lv_w  = (const float*)d_in[8];
    const float* lv_b  = (const float*)d_in[9];
    const float* g0_w  = (const float*)d_in[10];
    const float* g0_b  = (const float*)d_in[11];
    const float* g1_w  = (const float*)d_in[12];
    const float* g1_b  = (const float*)d_in[13];
    const float* g2_w  = (const float*)d_in[14];
    const float* g2_b  = (const float*)d_in[15];
    const float* w0    = (const float*)d_in[16];
    const float* b0    = (const float*)d_in[17];
    const float* w1    = (const float*)d_in[18];
    const float* b1    = (const float*)d_in[19];
    const float* w2    = (const float*)d_in[20];
    const float* b2    = (const float*)d_in[21];

    float* out       = (float*)d_out;
    float* out_layer = out;
    float* out_mu    = out + B_ * F_;
    float* out_lv    = out + B_ * F_ + B_ * L_;

    __nv_bfloat16* eAh = (__nv_bfloat16*)sym(g_encAh);
    __nv_bfloat16* eAl = (__nv_bfloat16*)sym(g_encAl);
    __nv_bfloat16* eBh = (__nv_bfloat16*)sym(g_encBh);
    __nv_bfloat16* eBl = (__nv_bfloat16*)sym(g_encBl);
    __nv_bfloat16* zch = (__nv_bfloat16*)sym(g_zch);
    __nv_bfloat16* zcl = (__nv_bfloat16*)sym(g_zcl);
    float* z     = (float*)sym(g_z);
    float* zc    = (float*)sym(g_zc);
    float* g0o   = (float*)sym(g_g0o);
    float* coef  = (float*)sym(g_coef);
    float* d0    = (float*)sym(g_d0);
    float* d1    = (float*)sym(g_d1);
    float* part  = (float*)sym(g_part);
    float* bmulv = (float*)sym(g_bmulv);
    float* wg1   = (float*)sym(g_wg1);
    __nv_bfloat16* we1h = (__nv_bfloat16*)sym(g_wte1h);
    __nv_bfloat16* we1l = (__nv_bfloat16*)sym(g_wte1l);
    __nv_bfloat16* we2h = (__nv_bfloat16*)sym(g_wte2h);
    __nv_bfloat16* we2l = (__nv_bfloat16*)sym(g_wte2l);
    __nv_bfloat16* wmvh = (__nv_bfloat16*)sym(g_wtmvh);
    __nv_bfloat16* wmvl = (__nv_bfloat16*)sym(g_wtmvl);
    __nv_bfloat16* wg0h = (__nv_bfloat16*)sym(g_wg0th);
    __nv_bfloat16* wg0l = (__nv_bfloat16*)sym(g_wg0tl);
    __nv_bfloat16* wt0h = (__nv_bfloat16*)sym(g_wt0h);
    __nv_bfloat16* wt0l = (__nv_bfloat16*)sym(g_wt0l);
    __nv_bfloat16* wt1h = (__nv_bfloat16*)sym(g_wt1h);
    __nv_bfloat16* wt1l = (__nv_bfloat16*)sym(g_wt1l);
    __nv_bfloat16* wt2h = (__nv_bfloat16*)sym(g_wt2h);
    __nv_bfloat16* wt2l = (__nv_bfloat16*)sym(g_wt2l);

    cudaFuncSetAttribute(tgemm<0>, cudaFuncAttributeMaxDynamicSharedMemorySize, TSM_TOTAL);
    cudaFuncSetAttribute(tgemm<1>, cudaFuncAttributeMaxDynamicSharedMemorySize, TSM_TOTAL);
    cudaFuncSetAttribute(tgemm<2>, cudaFuncAttributeMaxDynamicSharedMemorySize, TSM_TOTAL);
    cudaFuncSetAttribute(tgemm<0>, cudaFuncAttributePreferredSharedMemoryCarveout, 100);
    cudaFuncSetAttribute(tgemm<1>, cudaFuncAttributePreferredSharedMemoryCarveout, 100);
    cudaFuncSetAttribute(tgemm<2>, cudaFuncAttributePreferredSharedMemoryCarveout, 100);

    const int T = 256;
    auto gr = [](int n) { return (n + 255) / 256; };

    // one prep/pack launch
    megaprep<<<gr(MPTOT), T>>>(x, c, fc1_w, fc2_w, mu_w, mu_b, lv_w, lv_b, g0_w, g1_w,
                               w0, w1, w2, bmulv, wg1,
                               we1h, we1l, we2h, we2l, wmvh, wmvl, wg0h, wg0l,
                               wt0h, wt0l, wt1h, wt1l, wt2h, wt2l,
                               eAh, eAl, eBh, eBl, zc, zch, zcl);

    // ---- encoder fc1 (split-K 3) ----
    tgemm<0><<<dim3(4, 32, 3), T, TSM_TOTAL>>>(nullptr, KP_ENC, eAh, eAl, nullptr, nullptr,
                                               we1h, we1l, part, 256, (long)B_ * 256, KT_ENC, 3, KT_ENC);
    combine_h<<<gr(B_ * H_), T>>>(part, 3, eBh, eBl, fc1_b);

    // ---- encoder fc2 (split-K 3) ----
    tgemm<0><<<dim3(4, 32, 3), T, TSM_TOTAL>>>(nullptr, KP_ENC, eBh, eBl, nullptr, nullptr,
                                               we2h, we2l, part, 256, (long)B_ * 256, KT_ENC, 3, KT_ENC);
    combine_h<<<gr(B_ * H_), T>>>(part, 3, eBh, eBl, fc2_b);

    // ---- mu/lv (split-K 9) + fused z sampling ----
    tgemm<0><<<dim3(1, 32, 9), T, TSM_TOTAL>>>(nullptr, KP_ENC, eBh, eBl, nullptr, nullptr,
                                               wmvh, wmvl, part, 64, (long)B_ * 64, KT_ENC, 1, KT_ENC);
    combine_zeps<<<gr(B_ * L_), T>>>(part, 9, bmulv, z, zc, zch, zcl, out_mu, out_lv);

    // ---- gate: g0 tensor (split-K 5) + fused g1/g2/softmax ----
    tgemm<0><<<dim3(1, 32, 5), T, TSM_TOTAL>>>(nullptr, KP_G0, zch, zcl, nullptr, nullptr,
                                               wg0h, wg0l, part, 64, (long)B_ * 64, KT_G0, 1, KT_G0);
    combine<<<gr(B_ * G_), T>>>(part, 5, 64, g0o, G_, G_, g0_b, nullptr, nullptr, 0, 1);
    gate12<<<gr(B_ * 32), T>>>(g0o, wg1, g1_b, g2_w, g2_b, coef);

    // ---- decoder: split-K 4 ----
    tgemm<1><<<dim3(NT_L01, 32, 4), T, TSM_TOTAL>>>(zc, 0, nullptr, nullptr, nullptr, coef,
                                                    wt0h, wt0l, part, 256, (long)B_ * 256, KT_L0, 10, KT_L0);
    combine<<<gr(B_ * H_), T>>>(part, 4, 256, d0, H_, H_, nullptr, coef, b0, 256, 1);

    tgemm<2><<<dim3(NT_L01, 32, 4), T, TSM_TOTAL>>>(d0, 0, nullptr, nullptr, z, coef,
                                                    wt1h, wt1l, part, 256, (long)B_ * 256, KT_L12, 9, KT_L12);
    combine<<<gr(B_ * H_), T>>>(part, 4, 256, d1, H_, H_, nullptr, coef, b1, 256, 1);

    tgemm<2><<<dim3(NT_L2, 32, 4), T, TSM_TOTAL>>>(d1, 0, nullptr, nullptr, z, coef,
                                                   wt2h, wt2l, part, NP_W2, (long)B_ * NP_W2, KT_L12, 9, KT_L12);
    combine<<<gr(B_ * 267), T>>>(part, 4, NP_W2, out_layer, 267, 267, nullptr, coef, b2, 267, 0);
}

// round 16
// speedup vs baseline: 1.0585x; 1.0585x over previous
#include <cuda_runtime.h>
#include <cuda_bf16.h>
#include <cstdint>

// ---------------- problem dims ----------------
#define B_   2048
#define F_   267
#define L_   32
#define H_   256
#define E_   8
#define G_   64

#define KP_ENC 576
#define KP_ZC  304
#define KP_G0  320
#define IN1_   288
#define NP_W2  320

#define SPLIT_MAX 9

#define KT_ENC 9
#define KT_G0  5
#define KT_L0 38
#define KT_L12 36
#define NT_L01 4
#define NT_L2 5
#define WTE1_SZ (4*KT_ENC*4096)
#define WTE2_SZ (4*KT_ENC*4096)
#define WTMV_SZ (1*KT_ENC*4096)
#define WG0T_SZ (1*KT_G0*4096)
#define WT0_SZ (NT_L01*KT_L0*4096)
#define WT1_SZ (NT_L01*KT_L12*4096)
#define WT2_SZ (NT_L2*KT_L12*4096)

// ---------------- device scratch ----------------
__device__ __align__(16) __nv_bfloat16 g_encAh[B_*KP_ENC];
__device__ __align__(16) __nv_bfloat16 g_encAl[B_*KP_ENC];
__device__ __align__(16) __nv_bfloat16 g_encBh[B_*KP_ENC];
__device__ __align__(16) __nv_bfloat16 g_encBl[B_*KP_ENC];
__device__ __align__(16) __nv_bfloat16 g_zch  [B_*KP_G0];
__device__ __align__(16) __nv_bfloat16 g_zcl  [B_*KP_G0];
__device__ __align__(16) float g_z    [B_*L_];
__device__ __align__(16) float g_zc   [B_*KP_ZC];
__device__ __align__(16) float g_g0o  [B_*G_];
__device__ __align__(16) float g_coef [B_*E_];
__device__ __align__(16) float g_d0   [B_*H_];
__device__ __align__(16) float g_d1   [B_*H_];
__device__ __align__(16) float g_part [SPLIT_MAX*B_*NP_W2];
__device__ __align__(16) float g_bmulv[64];
__device__ __align__(16) float g_wg1  [G_*G_];
__device__ __align__(16) __nv_bfloat16 g_wte1h[WTE1_SZ];
__device__ __align__(16) __nv_bfloat16 g_wte1l[WTE1_SZ];
__device__ __align__(16) __nv_bfloat16 g_wte2h[WTE2_SZ];
__device__ __align__(16) __nv_bfloat16 g_wte2l[WTE2_SZ];
__device__ __align__(16) __nv_bfloat16 g_wtmvh[WTMV_SZ];
__device__ __align__(16) __nv_bfloat16 g_wtmvl[WTMV_SZ];
__device__ __align__(16) __nv_bfloat16 g_wg0th[WG0T_SZ];
__device__ __align__(16) __nv_bfloat16 g_wg0tl[WG0T_SZ];
__device__ __align__(16) __nv_bfloat16 g_wt0h[WT0_SZ];
__device__ __align__(16) __nv_bfloat16 g_wt0l[WT0_SZ];
__device__ __align__(16) __nv_bfloat16 g_wt1h[WT1_SZ];
__device__ __align__(16) __nv_bfloat16 g_wt1l[WT1_SZ];
__device__ __align__(16) __nv_bfloat16 g_wt2h[WT2_SZ];
__device__ __align__(16) __nv_bfloat16 g_wt2l[WT2_SZ];

__device__ __forceinline__ float elu1(float v) { return v > 0.f ? v : expm1f(v); }
__device__ __forceinline__ void split_bf16(float v, __nv_bfloat16& h, __nv_bfloat16& l) {
    h = __float2bfloat16(v);
    l = __float2bfloat16(v - __bfloat162float(h));
}

// ---------------- mma.sync + cp.async helpers ----------------
__device__ __forceinline__ uint32_t smem_u32(const void* p) {
    uint32_t a;
    asm("{ .reg .u64 t; cvta.to.shared.u64 t, %1; cvt.u32.u64 %0, t; }" : "=r"(a) : "l"(p));
    return a;
}
__device__ __forceinline__ void ldsm_x4(uint32_t* r, uint32_t addr) {
    asm volatile("ldmatrix.sync.aligned.m8n8.x4.shared.b16 {%0,%1,%2,%3}, [%4];"
                 : "=r"(r[0]), "=r"(r[1]), "=r"(r[2]), "=r"(r[3]) : "r"(addr));
}
__device__ __forceinline__ void mma16816(float* c, const uint32_t* a, const uint32_t* b) {
    asm volatile("mma.sync.aligned.m16n8k16.row.col.f32.bf16.bf16.f32 "
                 "{%0,%1,%2,%3}, {%4,%5,%6,%7}, {%8,%9}, {%0,%1,%2,%3};"
                 : "+f"(c[0]), "+f"(c[1]), "+f"(c[2]), "+f"(c[3])
                 : "r"(a[0]), "r"(a[1]), "r"(a[2]), "r"(a[3]), "r"(b[0]), "r"(b[1]));
}
__device__ __forceinline__ void cp16(uint32_t smem_dst, const void* gsrc) {
    asm volatile("cp.async.cg.shared.global [%0], [%1], 16;" :: "r"(smem_dst), "l"(gsrc));
}
#define CP_COMMIT() asm volatile("cp.async.commit_group;" ::: "memory")
#define CP_WAIT0()  asm volatile("cp.async.wait_group 0;" ::: "memory")

// ---------------- small pack (wg1 transposed + mulv bias) ----------------
#define PK3 64
#define PK5 (G_*G_)
#define PKTOT (PK3+PK5)

__global__ void pack_all(const float* __restrict__ mu_b, const float* __restrict__ lv_b,
                         const float* __restrict__ g1_w,
                         float* __restrict__ bmulv, float* __restrict__ wg1) {
    int idx = blockIdx.x * blockDim.x + threadIdx.x;
    if (idx >= PKTOT) return;
    if (idx < PK3) {
        bmulv[idx] = (idx < 32) ? mu_b[idx] : lv_b[idx - 32];
        return;
    } idx -= PK3;
    {
        int k = idx / G_, n = idx % G_;
        wg1[idx] = g1_w[n * G_ + k];
    }
}

// ---------------- tensor weight pack ----------------
__global__ void tpack(const float* __restrict__ fc1_w, const float* __restrict__ fc2_w,
                      const float* __restrict__ mu_w, const float* __restrict__ lv_w,
                      const float* __restrict__ g0_w,
                      const float* __restrict__ w0, const float* __restrict__ w1,
                      const float* __restrict__ w2,
                      __nv_bfloat16* __restrict__ we1h, __nv_bfloat16* __restrict__ we1l,
                      __nv_bfloat16* __restrict__ we2h, __nv_bfloat16* __restrict__ we2l,
                      __nv_bfloat16* __restrict__ wmvh, __nv_bfloat16* __restrict__ wmvl,
                      __nv_bfloat16* __restrict__ wg0h, __nv_bfloat16* __restrict__ wg0l,
                      __nv_bfloat16* __restrict__ wt0h, __nv_bfloat16* __restrict__ wt0l,
                      __nv_bfloat16* __restrict__ wt1h, __nv_bfloat16* __restrict__ wt1l,
                      __nv_bfloat16* __restrict__ wt2h, __nv_bfloat16* __restrict__ wt2l) {
    int idx = blockIdx.x * blockDim.x + threadIdx.x;
    int layer, KT;
    __nv_bfloat16 *dh, *dl;
    if (idx < WTE1_SZ) { layer = 0; KT = KT_ENC; dh = we1h; dl = we1l; }
    else if (idx < WTE1_SZ + WTE2_SZ) { idx -= WTE1_SZ; layer = 1; KT = KT_ENC; dh = we2h; dl = we2l; }
    else if (idx < WTE1_SZ + WTE2_SZ + WTMV_SZ) { idx -= WTE1_SZ + WTE2_SZ; layer = 2; KT = KT_ENC; dh = wmvh; dl = wmvl; }
    else if (idx < WTE1_SZ + WTE2_SZ + WTMV_SZ + WG0T_SZ) { idx -= WTE1_SZ + WTE2_SZ + WTMV_SZ; layer = 6; KT = KT_G0; dh = wg0h; dl = wg0l; }
    else if (idx < WTE1_SZ + WTE2_SZ + WTMV_SZ + WG0T_SZ + WT0_SZ) { idx -= WTE1_SZ + WTE2_SZ + WTMV_SZ + WG0T_SZ; layer = 3; KT = KT_L0; dh = wt0h; dl = wt0l; }
    else if (idx < WTE1_SZ + WTE2_SZ + WTMV_SZ + WG0T_SZ + WT0_SZ + WT1_SZ) { idx -= WTE1_SZ + WTE2_SZ + WTMV_SZ + WG0T_SZ + WT0_SZ; layer = 4; KT = KT_L12; dh = wt1h; dl = wt1l; }
    else if (idx < WTE1_SZ + WTE2_SZ + WTMV_SZ + WG0T_SZ + WT0_SZ + WT1_SZ + WT2_SZ) { idx -= WTE1_SZ + WTE2_SZ + WTMV_SZ + WG0T_SZ + WT0_SZ + WT1_SZ; layer = 5; KT = KT_L12; dh = wt2h; dl = wt2l; }
    else return;
    int tile = idx >> 12, u = idx & 4095;
    int ntile = tile / KT, kt = tile % KT;
    int nrow = u >> 6, kc = u & 63;
    int n = ntile * 64 + nrow;
    int kg = kt * 64 + kc;
    float w = 0.f;
    if (layer == 0) {
        if (kg < 534) w = fc1_w[(size_t)n * 534 + kg];
    } else if (layer == 1) {
        if (kg < 523) w = fc2_w[(size_t)n * 523 + kg];
    } else if (layer == 2) {
        if (kg < 523) w = (n < 32) ? mu_w[(size_t)n * 523 + kg]
                                   : lv_w[(size_t)(n - 32) * 523 + kg];
    } else if (layer == 6) {
        if (kg < 299) w = g0_w[(size_t)n * 299 + kg];
    } else if (layer == 3) {
        int e = kg / KP_ZC, i = kg - e * KP_ZC;
        if (i < 299) w = w0[((size_t)(e * 299 + i)) * 256 + n];
    } else if (layer == 4) {
        w = w1[(size_t)kg * 256 + n];
    } else {
        if (n < 267) w = w2[(size_t)kg * 267 + n];
    }
    __nv_bfloat16 hi, lo;
    split_bf16(w, hi, lo);
    size_t dst = ((size_t)tile << 12) + u;
    dh[dst] = hi;
    dl[dst] = lo;
}

// ---------------- fused input-prep ----------------
#define PR0 (B_*KP_ENC)
#define PR1 (B_*320)
#define PR2 (B_*272)
#define PR3 (B_*288)
__global__ void prep_inputs(const float* __restrict__ x, const float* __restrict__ c,
                            __nv_bfloat16* __restrict__ eAh, __nv_bfloat16* __restrict__ eAl,
                            __nv_bfloat16* __restrict__ eBh, __nv_bfloat16* __restrict__ eBl,
                            float* __restrict__ zc,
                            __nv_bfloat16* __restrict__ zch, __nv_bfloat16* __restrict__ zcl) {
    int idx = blockIdx.x * blockDim.x + threadIdx.x;
    if (idx < PR0) {
        int b = idx / KP_ENC, k = idx % KP_ENC;
        float v = 0.f;
        if (k < 267)      v = x[b * 267 + k];
        else if (k < 534) v = c[b * 267 + (k - 267)];
        __nv_bfloat16 h, l;
        split_bf16(v, h, l);
        eAh[idx] = h;
        eAl[idx] = l;
        return;
    } idx -= PR0;
    if (idx < PR1) {
        int b = idx / 320, j = idx % 320;
        int k = (j < 267) ? j : (523 + (j - 267));
        float v = (j < 267) ? x[b * 267 + j] : 0.f;
        __nv_bfloat16 h, l;
        split_bf16(v, h, l);
        eBh[b * KP_ENC + k] = h;
        eBl[b * KP_ENC + k] = l;
        return;
    } idx -= PR1;
    if (idx < PR2) {
        int b = idx / 272, k = 32 + idx % 272;
        zc[b * KP_ZC + k] = (k < 299) ? c[b * 267 + (k - 32)] : 0.f;
        return;
    } idx -= PR2;
    if (idx < PR3) {
        int b = idx / 288, k = 32 + idx % 288;
        float v = (k < 299) ? c[b * 267 + (k - 32)] : 0.f;
        __nv_bfloat16 h, l;
        split_bf16(v, h, l);
        zch[b * KP_G0 + k] = h;
        zcl[b * KP_G0 + k] = l;
    }
}

// ---------------- threefry + erfinv ----------------
__device__ __forceinline__ uint32_t rotl32(uint32_t v, int d) { return (v << d) | (v >> (32 - d)); }
__device__ __forceinline__ void tf4(uint32_t& x0, uint32_t& x1, int r0, int r1, int r2, int r3) {
    x0 += x1; x1 = rotl32(x1, r0); x1 ^= x0;
    x0 += x1; x1 = rotl32(x1, r1); x1 ^= x0;
    x0 += x1; x1 = rotl32(x1, r2); x1 ^= x0;
    x0 += x1; x1 = rotl32(x1, r3); x1 ^= x0;
}
__device__ __forceinline__ void threefry2x32(uint32_t k0, uint32_t k1, uint32_t& x0, uint32_t& x1) {
    uint32_t k2 = k0 ^ k1 ^ 0x1BD11BDAu;
    x0 += k0; x1 += k1;
    tf4(x0, x1, 13, 15, 26, 6);  x0 += k1; x1 += k2 + 1u;
    tf4(x0, x1, 17, 29, 16, 24); x0 += k2; x1 += k0 + 2u;
    tf4(x0, x1, 13, 15, 26, 6);  x0 += k0; x1 += k1 + 3u;
    tf4(x0, x1, 17, 29, 16, 24); x0 += k1; x1 += k2 + 4u;
    tf4(x0, x1, 13, 15, 26, 6);  x0 += k2; x1 += k0 + 5u;
}
__device__ __forceinline__ float erfinv_xla(float x) {
    float w = -log1pf(-x * x);
    float p;
    if (w < 5.0f) {
        w -= 2.5f;
        p = 2.81022636e-08f;
        p = fmaf(p, w, 3.43273939e-07f);
        p = fmaf(p, w, -3.5233877e-06f);
        p = fmaf(p, w, -4.39150654e-06f);
        p = fmaf(p, w, 0.00021858087f);
        p = fmaf(p, w, -0.00125372503f);
        p = fmaf(p, w, -0.00417768164f);
        p = fmaf(p, w, 0.246640727f);
        p = fmaf(p, w, 1.50140941f);
    } else {
        w = sqrtf(w) - 3.0f;
        p = -0.000200214257f;
        p = fmaf(p, w, 0.000100950558f);
        p = fmaf(p, w, 0.00134934322f);
        p = fmaf(p, w, -0.00367342844f);
        p = fmaf(p, w, 0.00573950773f);
        p = fmaf(p, w, -0.0076224613f);
        p = fmaf(p, w, 0.00943887047f);
        p = fmaf(p, w, 1.00167406f);
        p = fmaf(p, w, 2.83297682f);
    }
    return p * x;
}

__global__ void combine_zeps(const float* __restrict__ part, int S,
                             const float* __restrict__ bmulv,
                             float* __restrict__ zout, float* __restrict__ zc,
                             __nv_bfloat16* __restrict__ zch, __nv_bfloat16* __restrict__ zcl,
                             float* __restrict__ out_mu, float* __restrict__ out_lv) {
    int i = blockIdx.x * blockDim.x + threadIdx.x;
    if (i >= B_ * L_) return;
    int b = i >> 5, l = i & 31;
    float mu = bmulv[l], lv = bmulv[32 + l];
    for (int s = 0; s < S; s++) {
        const float* p = part + (size_t)s * B_ * 64 + (size_t)b * 64;
        mu += p[l];
        lv += p[32 + l];
    }
    uint32_t x0 = 0u, x1 = (uint32_t)i;
    threefry2x32(0u, 42u, x0, x1);
    uint32_t bits = x0 ^ x1;
    float f = __uint_as_float((bits >> 9) | 0x3f800000u) - 1.0f;
    const float lo = -0.99999994f;
    float u = fmaxf(lo, fmaf(f, 2.0f, lo));
    float eps = 1.41421354f * erfinv_xla(u);
    float zv = fmaf(eps, expf(0.5f * lv), mu);
    zout[i] = zv;
    zc[b * KP_ZC + l] = zv;
    __nv_bfloat16 h, l2;
    split_bf16(zv, h, l2);
    zch[b * KP_G0 + l] = h;
    zcl[b * KP_G0 + l] = l2;
    out_mu[i] = mu;
    out_lv[i] = lv;
}

// ---------------- fused gate g1 + g2 + softmax ----------------
__global__ void gate12(const float* __restrict__ g0o,
                       const float* __restrict__ wg1,
                       const float* __restrict__ g1_b,
                       const float* __restrict__ g2w,
                       const float* __restrict__ g2b,
                       float* __restrict__ coeff) {
    int gtid = blockIdx.x * blockDim.x + threadIdx.x;
    int row = gtid >> 5, lane = gtid & 31;
    if (row >= B_) return;
    float v0 = g0o[row * G_ + lane];
    float v1 = g0o[row * G_ + 32 + lane];
    float h0 = g1_b[lane], h1 = g1_b[32 + lane];
    #pragma unroll
    for (int k = 0; k < 32; k++) {
        float a0 = __shfl_sync(0xffffffffu, v0, k);
        float a1 = __shfl_sync(0xffffffffu, v1, k);
        h0 = fmaf(a0, wg1[k * G_ + lane], h0);
        h1 = fmaf(a0, wg1[k * G_ + 32 + lane], h1);
        h0 = fmaf(a1, wg1[(32 + k) * G_ + lane], h0);
        h1 = fmaf(a1, wg1[(32 + k) * G_ + 32 + lane], h1);
    }
    h0 = elu1(h0);
    h1 = elu1(h1);
    float lg[E_];
    #pragma unroll
    for (int e = 0; e < E_; e++) {
        float p = fmaf(h0, g2w[e * G_ + lane], h1 * g2w[e * G_ + 32 + lane]);
        #pragma unroll
        for (int d = 16; d > 0; d >>= 1) p += __shfl_xor_sync(0xffffffffu, p, d);
        lg[e] = p + g2b[e];
    }
    float m = lg[0];
    #pragma unroll
    for (int e = 1; e < E_; e++) m = fmaxf(m, lg[e]);
    float s = 0.f;
    #pragma unroll
    for (int e = 0; e < E_; e++) { lg[e] = expf(lg[e] - m); s += lg[e]; }
    if (lane < E_) coeff[row * E_ + lane] = lg[lane] / s;
}

// ---------------- mma.sync GEMM: BM=64, BN=64, double-buffered cp.async ----------------
#define LDS_AB 144
#define TS_A 9216
#define TS_B 9216
#define TSTAGE (2*TS_A + 2*TS_B)      // 36864
#define TSM_TOTAL (2*TSTAGE)          // 73728

template <int MODE>
__global__ void __launch_bounds__(256) tgemm(
    const float* __restrict__ src, int lda,
    const __nv_bfloat16* __restrict__ ah, const __nv_bfloat16* __restrict__ al,
    const float* __restrict__ z,
    const float* __restrict__ coeff,
    const __nv_bfloat16* __restrict__ wth,
    const __nv_bfloat16* __restrict__ wtl,
    float* __restrict__ C, int ldc, long sliceStride,
    int ktTot, int ktPer, int KT)
{
    extern __shared__ __align__(16) char smem[];
    uint32_t sb = smem_u32(smem);
    int tid = threadIdx.x;
    int wid = tid >> 5, lane = tid & 31;
    int wm = wid >> 1, wn = wid & 1;
    int m0 = blockIdx.y * 64;
    int ntile = blockIdx.x, n0 = ntile * 64;
    int kt0 = blockIdx.z * ktPer;
    int ktn = min(ktPer, ktTot - kt0);
    float* Cp = C + (long)blockIdx.z * sliceStride;

    float acc[4][4];
    #pragma unroll
    for (int nt = 0; nt < 4; nt++)
        #pragma unroll
        for (int j = 0; j < 4; j++) acc[nt][j] = 0.f;

    auto fill = [&](int kt, int buf) {
        uint32_t st = sb + buf * TSTAGE;
        if (MODE == 0) {
            #pragma unroll
            for (int gq = 0; gq < 4; gq++) {
                int g = tid + gq * 256;
                int sel = g >> 9;
                int r = (g >> 3) & 63, seg = g & 7;
                const __nv_bfloat16* srcp = (sel ? al : ah) + (size_t)(m0 + r) * lda + (kt << 6) + (seg << 3);
                cp16(st + sel * TS_A + r * LDS_AB + seg * 16, srcp);
            }
        } else {
            char* stc = smem + buf * TSTAGE;
            #pragma unroll
            for (int gq = 0; gq < 2; gq++) {
                int g = tid + gq * 256;
                int row = g >> 3, c8 = g & 7;
                int m = m0 + row;
                int kg = (kt << 6) + (c8 << 3);
                float4 f0, f1;
                float cf;
                if (MODE == 1) {
                    int e = kg / KP_ZC, i = kg - e * KP_ZC;
                    cf = coeff[m * E_ + e];
                    f0 = *(const float4*)(src + (size_t)m * KP_ZC + i);
                    f1 = *(const float4*)(src + (size_t)m * KP_ZC + i + 4);
                } else {
                    int e = kg / IN1_, i = kg - e * IN1_;
                    cf = coeff[m * E_ + e];
                    if (i < L_) {
                        f0 = *(const float4*)(z + (size_t)m * L_ + i);
                        f1 = *(const float4*)(z + (size_t)m * L_ + i + 4);
                    } else {
                        f0 = *(const float4*)(src + (size_t)m * H_ + (i - L_));
                        f1 = *(const float4*)(src + (size_t)m * H_ + (i - L_) + 4);
                    }
                }
                float v[8] = { cf * f0.x, cf * f0.y, cf * f0.z, cf * f0.w,
                               cf * f1.x, cf * f1.y, cf * f1.z, cf * f1.w };
                union { __nv_bfloat16 b[8]; uint4 u; } hv, lv;
                #pragma unroll
                for (int j = 0; j < 8; j++) split_bf16(v[j], hv.b[j], lv.b[j]);
                *(uint4*)(stc + row * LDS_AB + c8 * 16) = hv.u;
                *(uint4*)(stc + TS_A + row * LDS_AB + c8 * 16) = lv.u;
            }
        }
        const __nv_bfloat16* th = wth + ((size_t)(ntile * KT + kt) << 12);
        const __nv_bfloat16* tl = wtl + ((size_t)(ntile * KT + kt) << 12);
        #pragma unroll
        for (int gq = 0; gq < 2; gq++) {
            int g = tid + gq * 256;
            int n = g >> 3, seg = g & 7;
            cp16(st + 2 * TS_A + n * LDS_AB + seg * 16, th + n * 64 + seg * 8);
            cp16(st + 2 * TS_A + TS_B + n * LDS_AB + seg * 16, tl + n * 64 + seg * 8);
        }
    };

    fill(kt0, 0);
    CP_COMMIT();
    CP_WAIT0();
    __syncthreads();

    for (int t = 0; t < ktn; t++) {
        int buf = t & 1;
        bool more = (t + 1) < ktn;
        if (more) {
            fill(kt0 + t + 1, buf ^ 1);
            CP_COMMIT();
        }

        uint32_t sA = sb + buf * TSTAGE;
        uint32_t sB = sA + 2 * TS_A;
        int arow = wm * 16 + (lane & 15);
        int bn = wn * 32 + ((lane >> 4) << 3) + (lane & 7);
        int bkl = ((lane >> 3) & 1) << 3;
        #pragma unroll
        for (int ks = 0; ks < 4; ks++) {
            uint32_t ahf[4], alf[4];
            uint32_t bh0[4], bh1[4], bl0[4], bl1[4];
            uint32_t aAdr = sA + arow * LDS_AB + (ks * 16 + (lane >> 4) * 8) * 2;
            ldsm_x4(ahf, aAdr);
            ldsm_x4(alf, aAdr + TS_A);
            uint32_t bAdr = sB + bn * LDS_AB + (ks * 16 + bkl) * 2;
            ldsm_x4(bh0, bAdr);
            ldsm_x4(bh1, bAdr + 16 * LDS_AB);
            ldsm_x4(bl0, bAdr + TS_B);
            ldsm_x4(bl1, bAdr + TS_B + 16 * LDS_AB);

            mma16816(acc[0], ahf, bh0);     mma16816(acc[1], ahf, bh0 + 2);
            mma16816(acc[2], ahf, bh1);     mma16816(acc[3], ahf, bh1 + 2);

            mma16816(acc[0], ahf, bl0);     mma16816(acc[1], ahf, bl0 + 2);
            mma16816(acc[2], ahf, bl1);     mma16816(acc[3], ahf, bl1 + 2);

            mma16816(acc[0], alf, bh0);     mma16816(acc[1], alf, bh0 + 2);
            mma16816(acc[2], alf, bh1);     mma16816(acc[3], alf, bh1 + 2);
        }
        if (more) CP_WAIT0();
        __syncthreads();
    }

    #pragma unroll
    for (int nt = 0; nt < 4; nt++) {
        int m = m0 + wm * 16 + (lane >> 2);
        int n = n0 + wn * 32 + nt * 8 + ((lane & 3) << 1);
        *(float2*)(Cp + (size_t)m * ldc + n) = make_float2(acc[nt][0], acc[nt][1]);
        *(float2*)(Cp + (size_t)(m + 8) * ldc + n) = make_float2(acc[nt][2], acc[nt][3]);
    }
}

// ---------------- split-K combines ----------------
__global__ void combine(const float* __restrict__ part, int S, int ldp,
                        float* __restrict__ C, int ldc, int Nout,
                        const float* __restrict__ bias,
                        const float* __restrict__ coeff,
                        const float* __restrict__ ebias, int ebld,
                        int act)
{
    int idx = blockIdx.x * blockDim.x + threadIdx.x;
    if (idx >= B_ * Nout) return;
    int m = idx / Nout, n = idx % Nout;
    float v = 0.f;
    for (int s = 0; s < S; s++) v += part[(size_t)s * B_ * ldp + (size_t)m * ldp + n];
    if (bias) v += bias[n];
    if (ebias) {
        const float* cf = coeff + m * E_;
        float bm = 0.f;
        #pragma unroll
        for (int e = 0; e < E_; e++) bm = fmaf(cf[e], ebias[e * ebld + n], bm);
        v += bm;
    }
    if (act) v = elu1(v);
    C[(size_t)m * ldc + n] = v;
}

__global__ void combine_h(const float* __restrict__ part, int S,
                          __nv_bfloat16* __restrict__ Ch, __nv_bfloat16* __restrict__ Cl,
                          const float* __restrict__ bias)
{
    int idx = blockIdx.x * blockDim.x + threadIdx.x;
    if (idx >= B_ * H_) return;
    int m = idx / H_, n = idx % H_;
    float v = bias[n];
    for (int s = 0; s < S; s++) v += part[(size_t)s * B_ * 256 + (size_t)m * 256 + n];
    v = elu1(v);
    __nv_bfloat16 h, l;
    split_bf16(v, h, l);
    size_t dst = (size_t)m * KP_ENC + 267 + n;
    Ch[dst] = h;
    Cl[dst] = l;
}

// ---------------- host launch ----------------
static inline void* sym(const void* s) { void* p = nullptr; cudaGetSymbolAddress(&p, s); return p; }

extern "C" void kernel_launch(void* const* d_in, const int* in_sizes, int n_in,
                              void* d_out, int out_size) {
    (void)in_sizes; (void)n_in; (void)out_size;
    const float* x     = (const float*)d_in[0];
    const float* c     = (const float*)d_in[1];
    const float* fc1_w = (const float*)d_in[2];
    const float* fc1_b = (const float*)d_in[3];
    const float* fc2_w = (const float*)d_in[4];
    const float* fc2_b = (const float*)d_in[5];
    const float* mu_w  = (const float*)d_in[6];
    const float* mu_b  = (const float*)d_in[7];
    const float* lv_w  = (const float*)d_in[8];
    const float* lv_b  = (const float*)d_in[9];
    const float* g0_w  = (const float*)d_in[10];
    const float* g0_b  = (const float*)d_in[11];
    const float* g1_w  = (const float*)d_in[12];
    const float* g1_b  = (const float*)d_in[13];
    const float* g2_w  = (const float*)d_in[14];
    const float* g2_b  = (const float*)d_in[15];
    const float* w0    = (const float*)d_in[16];
    const float* b0    = (const float*)d_in[17];
    const float* w1    = (const float*)d_in[18];
    const float* b1    = (const float*)d_in[19];
    const float* w2    = (const float*)d_in[20];
    const float* b2    = (const float*)d_in[21];

    float* out       = (float*)d_out;
    float* out_layer = out;
    float* out_mu    = out + B_ * F_;
    float* out_lv    = out + B_ * F_ + B_ * L_;

    __nv_bfloat16* eAh = (__nv_bfloat16*)sym(g_encAh);
    __nv_bfloat16* eAl = (__nv_bfloat16*)sym(g_encAl);
    __nv_bfloat16* eBh = (__nv_bfloat16*)sym(g_encBh);
    __nv_bfloat16* eBl = (__nv_bfloat16*)sym(g_encBl);
    __nv_bfloat16* zch = (__nv_bfloat16*)sym(g_zch);
    __nv_bfloat16* zcl = (__nv_bfloat16*)sym(g_zcl);
    float* z     = (float*)sym(g_z);
    float* zc    = (float*)sym(g_zc);
    float* g0o   = (float*)sym(g_g0o);
    float* coef  = (float*)sym(g_coef);
    float* d0    = (float*)sym(g_d0);
    float* d1    = (float*)sym(g_d1);
    float* part  = (float*)sym(g_part);
    float* bmulv = (float*)sym(g_bmulv);
    float* wg1   = (float*)sym(g_wg1);
    __nv_bfloat16* we1h = (__nv_bfloat16*)sym(g_wte1h);
    __nv_bfloat16* we1l = (__nv_bfloat16*)sym(g_wte1l);
    __nv_bfloat16* we2h = (__nv_bfloat16*)sym(g_wte2h);
    __nv_bfloat16* we2l = (__nv_bfloat16*)sym(g_wte2l);
    __nv_bfloat16* wmvh = (__nv_bfloat16*)sym(g_wtmvh);
    __nv_bfloat16* wmvl = (__nv_bfloat16*)sym(g_wtmvl);
    __nv_bfloat16* wg0h = (__nv_bfloat16*)sym(g_wg0th);
    __nv_bfloat16* wg0l = (__nv_bfloat16*)sym(g_wg0tl);
    __nv_bfloat16* wt0h = (__nv_bfloat16*)sym(g_wt0h);
    __nv_bfloat16* wt0l = (__nv_bfloat16*)sym(g_wt0l);
    __nv_bfloat16* wt1h = (__nv_bfloat16*)sym(g_wt1h);
    __nv_bfloat16* wt1l = (__nv_bfloat16*)sym(g_wt1l);
    __nv_bfloat16* wt2h = (__nv_bfloat16*)sym(g_wt2h);
    __nv_bfloat16* wt2l = (__nv_bfloat16*)sym(g_wt2l);

    cudaFuncSetAttribute(tgemm<0>, cudaFuncAttributeMaxDynamicSharedMemorySize, TSM_TOTAL);
    cudaFuncSetAttribute(tgemm<1>, cudaFuncAttributeMaxDynamicSharedMemorySize, TSM_TOTAL);
    cudaFuncSetAttribute(tgemm<2>, cudaFuncAttributeMaxDynamicSharedMemorySize, TSM_TOTAL);
    cudaFuncSetAttribute(tgemm<0>, cudaFuncAttributePreferredSharedMemoryCarveout, 100);
    cudaFuncSetAttribute(tgemm<1>, cudaFuncAttributePreferredSharedMemoryCarveout, 100);
    cudaFuncSetAttribute(tgemm<2>, cudaFuncAttributePreferredSharedMemoryCarveout, 100);

    const int T = 256;
    auto gr = [](int n) { return (n + 255) / 256; };

    pack_all<<<gr(PKTOT), T>>>(mu_b, lv_b, g1_w, bmulv, wg1);
    tpack<<<gr(WTE1_SZ + WTE2_SZ + WTMV_SZ + WG0T_SZ + WT0_SZ + WT1_SZ + WT2_SZ), T>>>(
        fc1_w, fc2_w, mu_w, lv_w, g0_w, w0, w1, w2,
        we1h, we1l, we2h, we2l, wmvh, wmvl, wg0h, wg0l,
        wt0h, wt0l, wt1h, wt1l, wt2h, wt2l);
    prep_inputs<<<gr(PR0 + PR1 + PR2 + PR3), T>>>(x, c, eAh, eAl, eBh, eBl, zc, zch, zcl);

    // ---- encoder fc1 (split-K 3) ----
    tgemm<0><<<dim3(4, 32, 3), T, TSM_TOTAL>>>(nullptr, KP_ENC, eAh, eAl, nullptr, nullptr,
                                               we1h, we1l, part, 256, (long)B_ * 256, KT_ENC, 3, KT_ENC);
    combine_h<<<gr(B_ * H_), T>>>(part, 3, eBh, eBl, fc1_b);

    // ---- encoder fc2 (split-K 3) ----
    tgemm<0><<<dim3(4, 32, 3), T, TSM_TOTAL>>>(nullptr, KP_ENC, eBh, eBl, nullptr, nullptr,
                                               we2h, we2l, part, 256, (long)B_ * 256, KT_ENC, 3, KT_ENC);
    combine_h<<<gr(B_ * H_), T>>>(part, 3, eBh, eBl, fc2_b);

    // ---- mu/lv (split-K 9) + fused z sampling ----
    tgemm<0><<<dim3(1, 32, 9), T, TSM_TOTAL>>>(nullptr, KP_ENC, eBh, eBl, nullptr, nullptr,
                                               wmvh, wmvl, part, 64, (long)B_ * 64, KT_ENC, 1, KT_ENC);
    combine_zeps<<<gr(B_ * L_), T>>>(part, 9, bmulv, z, zc, zch, zcl, out_mu, out_lv);

    // ---- gate: g0 tensor (split-K 5) + fused g1/g2/softmax ----
    tgemm<0><<<dim3(1, 32, 5), T, TSM_TOTAL>>>(nullptr, KP_G0, zch, zcl, nullptr, nullptr,
                                               wg0h, wg0l, part, 64, (long)B_ * 64, KT_G0, 1, KT_G0);
    combine<<<gr(B_ * G_), T>>>(part, 5, 64, g0o, G_, G_, g0_b, nullptr, nullptr, 0, 1);
    gate12<<<gr(B_ * 32), T>>>(g0o, wg1, g1_b, g2_w, g2_b, coef);

    // ---- decoder: split-K 8 ----
    tgemm<1><<<dim3(NT_L01, 32, 8), T, TSM_TOTAL>>>(zc, 0, nullptr, nullptr, nullptr, coef,
                                                    wt0h, wt0l, part, 256, (long)B_ * 256, KT_L0, 5, KT_L0);
    combine<<<gr(B_ * H_), T>>>(part, 8, 256, d0, H_, H_, nullptr, coef, b0, 256, 1);

    tgemm<2><<<dim3(NT_L01, 32, 8), T, TSM_TOTAL>>>(d0, 0, nullptr, nullptr, z, coef,
                                                    wt1h, wt1l, part, 256, (long)B_ * 256, KT_L12, 5, KT_L12);
    combine<<<gr(B_ * H_), T>>>(part, 8, 256, d1, H_, H_, nullptr, coef, b1, 256, 1);

    tgemm<2><<<dim3(NT_L2, 32, 8), T, TSM_TOTAL>>>(d1, 0, nullptr, nullptr, z, coef,
                                                   wt2h, wt2l, part, NP_W2, (long)B_ * NP_W2, KT_L12, 5, KT_L12);
    combine<<<gr(B_ * 267), T>>>(part, 8, NP_W2, out_layer, 267, 267, nullptr, coef, b2, 267, 0);
}

// round 17
// speedup vs baseline: 1.0644x; 1.0055x over previous
#include <cuda_runtime.h>
#include <cuda_bf16.h>
#include <cstdint>

// ---------------- problem dims ----------------
#define B_   2048
#define F_   267
#define L_   32
#define H_   256
#define E_   8
#define G_   64

#define KP_ENC 576
#define KP_ZC  304
#define KP_G0  320
#define IN1_   288
#define NP_W2  320

#define SPLIT_MAX 9

#define KT_ENC 9
#define KT_G0  5
#define KT_L0 38
#define KT_L12 36
#define NT_L01 4
#define NT_L2 5
#define WTE1_SZ (4*KT_ENC*4096)
#define WTE2_SZ (4*KT_ENC*4096)
#define WTMV_SZ (1*KT_ENC*4096)
#define WG0T_SZ (1*KT_G0*4096)
#define WT0_SZ (NT_L01*KT_L0*4096)
#define WT1_SZ (NT_L01*KT_L12*4096)
#define WT2_SZ (NT_L2*KT_L12*4096)

// ---------------- device scratch ----------------
__device__ __align__(16) __nv_bfloat16 g_encAh[B_*KP_ENC];
__device__ __align__(16) __nv_bfloat16 g_encAl[B_*KP_ENC];
__device__ __align__(16) __nv_bfloat16 g_encBh[B_*KP_ENC];
__device__ __align__(16) __nv_bfloat16 g_encBl[B_*KP_ENC];
__device__ __align__(16) __nv_bfloat16 g_zch  [B_*KP_G0];
__device__ __align__(16) __nv_bfloat16 g_zcl  [B_*KP_G0];
__device__ __align__(16) float g_z    [B_*L_];
__device__ __align__(16) float g_zc   [B_*KP_ZC];
__device__ __align__(16) float g_g0o  [B_*G_];
__device__ __align__(16) float g_coef [B_*E_];
__device__ __align__(16) float g_d0   [B_*H_];
__device__ __align__(16) float g_d1   [B_*H_];
__device__ __align__(16) float g_part [SPLIT_MAX*B_*NP_W2];
__device__ __align__(16) float g_bmulv[64];
__device__ __align__(16) float g_wg1  [G_*G_];
__device__ __align__(16) __nv_bfloat16 g_wte1h[WTE1_SZ];
__device__ __align__(16) __nv_bfloat16 g_wte1l[WTE1_SZ];
__device__ __align__(16) __nv_bfloat16 g_wte2h[WTE2_SZ];
__device__ __align__(16) __nv_bfloat16 g_wte2l[WTE2_SZ];
__device__ __align__(16) __nv_bfloat16 g_wtmvh[WTMV_SZ];
__device__ __align__(16) __nv_bfloat16 g_wtmvl[WTMV_SZ];
__device__ __align__(16) __nv_bfloat16 g_wg0th[WG0T_SZ];
__device__ __align__(16) __nv_bfloat16 g_wg0tl[WG0T_SZ];
__device__ __align__(16) __nv_bfloat16 g_wt0h[WT0_SZ];
__device__ __align__(16) __nv_bfloat16 g_wt0l[WT0_SZ];
__device__ __align__(16) __nv_bfloat16 g_wt1h[WT1_SZ];
__device__ __align__(16) __nv_bfloat16 g_wt1l[WT1_SZ];
__device__ __align__(16) __nv_bfloat16 g_wt2h[WT2_SZ];
__device__ __align__(16) __nv_bfloat16 g_wt2l[WT2_SZ];

__device__ __forceinline__ float elu1(float v) { return v > 0.f ? v : expm1f(v); }
__device__ __forceinline__ void split_bf16(float v, __nv_bfloat16& h, __nv_bfloat16& l) {
    h = __float2bfloat16(v);
    l = __float2bfloat16(v - __bfloat162float(h));
}

// ---------------- mma.sync + cp.async helpers ----------------
__device__ __forceinline__ uint32_t smem_u32(const void* p) {
    uint32_t a;
    asm("{ .reg .u64 t; cvta.to.shared.u64 t, %1; cvt.u32.u64 %0, t; }" : "=r"(a) : "l"(p));
    return a;
}
__device__ __forceinline__ void ldsm_x4(uint32_t* r, uint32_t addr) {
    asm volatile("ldmatrix.sync.aligned.m8n8.x4.shared.b16 {%0,%1,%2,%3}, [%4];"
                 : "=r"(r[0]), "=r"(r[1]), "=r"(r[2]), "=r"(r[3]) : "r"(addr));
}
__device__ __forceinline__ void mma16816(float* c, const uint32_t* a, const uint32_t* b) {
    asm volatile("mma.sync.aligned.m16n8k16.row.col.f32.bf16.bf16.f32 "
                 "{%0,%1,%2,%3}, {%4,%5,%6,%7}, {%8,%9}, {%0,%1,%2,%3};"
                 : "+f"(c[0]), "+f"(c[1]), "+f"(c[2]), "+f"(c[3])
                 : "r"(a[0]), "r"(a[1]), "r"(a[2]), "r"(a[3]), "r"(b[0]), "r"(b[1]));
}
__device__ __forceinline__ void cp16(uint32_t smem_dst, const void* gsrc) {
    asm volatile("cp.async.cg.shared.global [%0], [%1], 16;" :: "r"(smem_dst), "l"(gsrc));
}
#define CP_COMMIT() asm volatile("cp.async.commit_group;" ::: "memory")
#define CP_WAIT0()  asm volatile("cp.async.wait_group 0;" ::: "memory")

// ---------------- small pack (wg1 transposed + mulv bias) ----------------
#define PK3 64
#define PK5 (G_*G_)
#define PKTOT (PK3+PK5)

__global__ void pack_all(const float* __restrict__ mu_b, const float* __restrict__ lv_b,
                         const float* __restrict__ g1_w,
                         float* __restrict__ bmulv, float* __restrict__ wg1) {
    int idx = blockIdx.x * blockDim.x + threadIdx.x;
    if (idx >= PKTOT) return;
    if (idx < PK3) {
        bmulv[idx] = (idx < 32) ? mu_b[idx] : lv_b[idx - 32];
        return;
    } idx -= PK3;
    {
        int k = idx / G_, n = idx % G_;
        wg1[idx] = g1_w[n * G_ + k];
    }
}

// ---------------- tensor weight pack ----------------
__global__ void tpack(const float* __restrict__ fc1_w, const float* __restrict__ fc2_w,
                      const float* __restrict__ mu_w, const float* __restrict__ lv_w,
                      const float* __restrict__ g0_w,
                      const float* __restrict__ w0, const float* __restrict__ w1,
                      const float* __restrict__ w2,
                      __nv_bfloat16* __restrict__ we1h, __nv_bfloat16* __restrict__ we1l,
                      __nv_bfloat16* __restrict__ we2h, __nv_bfloat16* __restrict__ we2l,
                      __nv_bfloat16* __restrict__ wmvh, __nv_bfloat16* __restrict__ wmvl,
                      __nv_bfloat16* __restrict__ wg0h, __nv_bfloat16* __restrict__ wg0l,
                      __nv_bfloat16* __restrict__ wt0h, __nv_bfloat16* __restrict__ wt0l,
                      __nv_bfloat16* __restrict__ wt1h, __nv_bfloat16* __restrict__ wt1l,
                      __nv_bfloat16* __restrict__ wt2h, __nv_bfloat16* __restrict__ wt2l) {
    int idx = blockIdx.x * blockDim.x + threadIdx.x;
    int layer, KT;
    __nv_bfloat16 *dh, *dl;
    if (idx < WTE1_SZ) { layer = 0; KT = KT_ENC; dh = we1h; dl = we1l; }
    else if (idx < WTE1_SZ + WTE2_SZ) { idx -= WTE1_SZ; layer = 1; KT = KT_ENC; dh = we2h; dl = we2l; }
    else if (idx < WTE1_SZ + WTE2_SZ + WTMV_SZ) { idx -= WTE1_SZ + WTE2_SZ; layer = 2; KT = KT_ENC; dh = wmvh; dl = wmvl; }
    else if (idx < WTE1_SZ + WTE2_SZ + WTMV_SZ + WG0T_SZ) { idx -= WTE1_SZ + WTE2_SZ + WTMV_SZ; layer = 6; KT = KT_G0; dh = wg0h; dl = wg0l; }
    else if (idx < WTE1_SZ + WTE2_SZ + WTMV_SZ + WG0T_SZ + WT0_SZ) { idx -= WTE1_SZ + WTE2_SZ + WTMV_SZ + WG0T_SZ; layer = 3; KT = KT_L0; dh = wt0h; dl = wt0l; }
    else if (idx < WTE1_SZ + WTE2_SZ + WTMV_SZ + WG0T_SZ + WT0_SZ + WT1_SZ) { idx -= WTE1_SZ + WTE2_SZ + WTMV_SZ + WG0T_SZ + WT0_SZ; layer = 4; KT = KT_L12; dh = wt1h; dl = wt1l; }
    else if (idx < WTE1_SZ + WTE2_SZ + WTMV_SZ + WG0T_SZ + WT0_SZ + WT1_SZ + WT2_SZ) { idx -= WTE1_SZ + WTE2_SZ + WTMV_SZ + WG0T_SZ + WT0_SZ + WT1_SZ; layer = 5; KT = KT_L12; dh = wt2h; dl = wt2l; }
    else return;
    int tile = idx >> 12, u = idx & 4095;
    int ntile = tile / KT, kt = tile % KT;
    int nrow = u >> 6, kc = u & 63;
    int n = ntile * 64 + nrow;
    int kg = kt * 64 + kc;
    float w = 0.f;
    if (layer == 0) {
        if (kg < 534) w = fc1_w[(size_t)n * 534 + kg];
    } else if (layer == 1) {
        if (kg < 523) w = fc2_w[(size_t)n * 523 + kg];
    } else if (layer == 2) {
        if (kg < 523) w = (n < 32) ? mu_w[(size_t)n * 523 + kg]
                                   : lv_w[(size_t)(n - 32) * 523 + kg];
    } else if (layer == 6) {
        if (kg < 299) w = g0_w[(size_t)n * 299 + kg];
    } else if (layer == 3) {
        int e = kg / KP_ZC, i = kg - e * KP_ZC;
        if (i < 299) w = w0[((size_t)(e * 299 + i)) * 256 + n];
    } else if (layer == 4) {
        w = w1[(size_t)kg * 256 + n];
    } else {
        if (n < 267) w = w2[(size_t)kg * 267 + n];
    }
    __nv_bfloat16 hi, lo;
    split_bf16(w, hi, lo);
    size_t dst = ((size_t)tile << 12) + u;
    dh[dst] = hi;
    dl[dst] = lo;
}

// ---------------- fused input-prep ----------------
#define PR0 (B_*KP_ENC)
#define PR1 (B_*320)
#define PR2 (B_*272)
#define PR3 (B_*288)
__global__ void prep_inputs(const float* __restrict__ x, const float* __restrict__ c,
                            __nv_bfloat16* __restrict__ eAh, __nv_bfloat16* __restrict__ eAl,
                            __nv_bfloat16* __restrict__ eBh, __nv_bfloat16* __restrict__ eBl,
                            float* __restrict__ zc,
                            __nv_bfloat16* __restrict__ zch, __nv_bfloat16* __restrict__ zcl) {
    int idx = blockIdx.x * blockDim.x + threadIdx.x;
    if (idx < PR0) {
        int b = idx / KP_ENC, k = idx % KP_ENC;
        float v = 0.f;
        if (k < 267)      v = x[b * 267 + k];
        else if (k < 534) v = c[b * 267 + (k - 267)];
        __nv_bfloat16 h, l;
        split_bf16(v, h, l);
        eAh[idx] = h;
        eAl[idx] = l;
        return;
    } idx -= PR0;
    if (idx < PR1) {
        int b = idx / 320, j = idx % 320;
        int k = (j < 267) ? j : (523 + (j - 267));
        float v = (j < 267) ? x[b * 267 + j] : 0.f;
        __nv_bfloat16 h, l;
        split_bf16(v, h, l);
        eBh[b * KP_ENC + k] = h;
        eBl[b * KP_ENC + k] = l;
        return;
    } idx -= PR1;
    if (idx < PR2) {
        int b = idx / 272, k = 32 + idx % 272;
        zc[b * KP_ZC + k] = (k < 299) ? c[b * 267 + (k - 32)] : 0.f;
        return;
    } idx -= PR2;
    if (idx < PR3) {
        int b = idx / 288, k = 32 + idx % 288;
        float v = (k < 299) ? c[b * 267 + (k - 32)] : 0.f;
        __nv_bfloat16 h, l;
        split_bf16(v, h, l);
        zch[b * KP_G0 + k] = h;
        zcl[b * KP_G0 + k] = l;
    }
}

// ---------------- threefry + erfinv ----------------
__device__ __forceinline__ uint32_t rotl32(uint32_t v, int d) { return (v << d) | (v >> (32 - d)); }
__device__ __forceinline__ void tf4(uint32_t& x0, uint32_t& x1, int r0, int r1, int r2, int r3) {
    x0 += x1; x1 = rotl32(x1, r0); x1 ^= x0;
    x0 += x1; x1 = rotl32(x1, r1); x1 ^= x0;
    x0 += x1; x1 = rotl32(x1, r2); x1 ^= x0;
    x0 += x1; x1 = rotl32(x1, r3); x1 ^= x0;
}
__device__ __forceinline__ void threefry2x32(uint32_t k0, uint32_t k1, uint32_t& x0, uint32_t& x1) {
    uint32_t k2 = k0 ^ k1 ^ 0x1BD11BDAu;
    x0 += k0; x1 += k1;
    tf4(x0, x1, 13, 15, 26, 6);  x0 += k1; x1 += k2 + 1u;
    tf4(x0, x1, 17, 29, 16, 24); x0 += k2; x1 += k0 + 2u;
    tf4(x0, x1, 13, 15, 26, 6);  x0 += k0; x1 += k1 + 3u;
    tf4(x0, x1, 17, 29, 16, 24); x0 += k1; x1 += k2 + 4u;
    tf4(x0, x1, 13, 15, 26, 6);  x0 += k2; x1 += k0 + 5u;
}
__device__ __forceinline__ float erfinv_xla(float x) {
    float w = -log1pf(-x * x);
    float p;
    if (w < 5.0f) {
        w -= 2.5f;
        p = 2.81022636e-08f;
        p = fmaf(p, w, 3.43273939e-07f);
        p = fmaf(p, w, -3.5233877e-06f);
        p = fmaf(p, w, -4.39150654e-06f);
        p = fmaf(p, w, 0.00021858087f);
        p = fmaf(p, w, -0.00125372503f);
        p = fmaf(p, w, -0.00417768164f);
        p = fmaf(p, w, 0.246640727f);
        p = fmaf(p, w, 1.50140941f);
    } else {
        w = sqrtf(w) - 3.0f;
        p = -0.000200214257f;
        p = fmaf(p, w, 0.000100950558f);
        p = fmaf(p, w, 0.00134934322f);
        p = fmaf(p, w, -0.00367342844f);
        p = fmaf(p, w, 0.00573950773f);
        p = fmaf(p, w, -0.0076224613f);
        p = fmaf(p, w, 0.00943887047f);
        p = fmaf(p, w, 1.00167406f);
        p = fmaf(p, w, 2.83297682f);
    }
    return p * x;
}

__global__ void combine_zeps(const float* __restrict__ part, int S,
                             const float* __restrict__ bmulv,
                             float* __restrict__ zout, float* __restrict__ zc,
                             __nv_bfloat16* __restrict__ zch, __nv_bfloat16* __restrict__ zcl,
                             float* __restrict__ out_mu, float* __restrict__ out_lv) {
    int i = blockIdx.x * blockDim.x + threadIdx.x;
    if (i >= B_ * L_) return;
    int b = i >> 5, l = i & 31;
    float mu = bmulv[l], lv = bmulv[32 + l];
    for (int s = 0; s < S; s++) {
        const float* p = part + (size_t)s * B_ * 64 + (size_t)b * 64;
        mu += p[l];
        lv += p[32 + l];
    }
    uint32_t x0 = 0u, x1 = (uint32_t)i;
    threefry2x32(0u, 42u, x0, x1);
    uint32_t bits = x0 ^ x1;
    float f = __uint_as_float((bits >> 9) | 0x3f800000u) - 1.0f;
    const float lo = -0.99999994f;
    float u = fmaxf(lo, fmaf(f, 2.0f, lo));
    float eps = 1.41421354f * erfinv_xla(u);
    float zv = fmaf(eps, expf(0.5f * lv), mu);
    zout[i] = zv;
    zc[b * KP_ZC + l] = zv;
    __nv_bfloat16 h, l2;
    split_bf16(zv, h, l2);
    zch[b * KP_G0 + l] = h;
    zcl[b * KP_G0 + l] = l2;
    out_mu[i] = mu;
    out_lv[i] = lv;
}

// ---------------- fused gate g1 + g2 + softmax ----------------
__global__ void gate12(const float* __restrict__ g0o,
                       const float* __restrict__ wg1,
                       const float* __restrict__ g1_b,
                       const float* __restrict__ g2w,
                       const float* __restrict__ g2b,
                       float* __restrict__ coeff) {
    int gtid = blockIdx.x * blockDim.x + threadIdx.x;
    int row = gtid >> 5, lane = gtid & 31;
    if (row >= B_) return;
    float v0 = g0o[row * G_ + lane];
    float v1 = g0o[row * G_ + 32 + lane];
    float h0 = g1_b[lane], h1 = g1_b[32 + lane];
    #pragma unroll
    for (int k = 0; k < 32; k++) {
        float a0 = __shfl_sync(0xffffffffu, v0, k);
        float a1 = __shfl_sync(0xffffffffu, v1, k);
        h0 = fmaf(a0, wg1[k * G_ + lane], h0);
        h1 = fmaf(a0, wg1[k * G_ + 32 + lane], h1);
        h0 = fmaf(a1, wg1[(32 + k) * G_ + lane], h0);
        h1 = fmaf(a1, wg1[(32 + k) * G_ + 32 + lane], h1);
    }
    h0 = elu1(h0);
    h1 = elu1(h1);
    float lg[E_];
    #pragma unroll
    for (int e = 0; e < E_; e++) {
        float p = fmaf(h0, g2w[e * G_ + lane], h1 * g2w[e * G_ + 32 + lane]);
        #pragma unroll
        for (int d = 16; d > 0; d >>= 1) p += __shfl_xor_sync(0xffffffffu, p, d);
        lg[e] = p + g2b[e];
    }
    float m = lg[0];
    #pragma unroll
    for (int e = 1; e < E_; e++) m = fmaxf(m, lg[e]);
    float s = 0.f;
    #pragma unroll
    for (int e = 0; e < E_; e++) { lg[e] = expf(lg[e] - m); s += lg[e]; }
    if (lane < E_) coeff[row * E_ + lane] = lg[lane] / s;
}

// ---------------- mma.sync GEMM: BM=64, BN=64, double-buffered cp.async ----------------
#define LDS_AB 144
#define TS_A 9216
#define TS_B 9216
#define TSTAGE (2*TS_A + 2*TS_B)      // 36864
#define TSM_TOTAL (2*TSTAGE)          // 73728

template <int MODE>
__global__ void __launch_bounds__(256) tgemm(
    const float* __restrict__ src, int lda,
    const __nv_bfloat16* __restrict__ ah, const __nv_bfloat16* __restrict__ al,
    const float* __restrict__ z,
    const float* __restrict__ coeff,
    const __nv_bfloat16* __restrict__ wth,
    const __nv_bfloat16* __restrict__ wtl,
    float* __restrict__ C, int ldc, long sliceStride,
    int ktTot, int ktPer, int KT)
{
    extern __shared__ __align__(16) char smem[];
    uint32_t sb = smem_u32(smem);
    int tid = threadIdx.x;
    int wid = tid >> 5, lane = tid & 31;
    int wm = wid >> 1, wn = wid & 1;
    int m0 = blockIdx.y * 64;
    int ntile = blockIdx.x, n0 = ntile * 64;
    int kt0 = blockIdx.z * ktPer;
    int ktn = min(ktPer, ktTot - kt0);
    float* Cp = C + (long)blockIdx.z * sliceStride;

    float acc[4][4];
    #pragma unroll
    for (int nt = 0; nt < 4; nt++)
        #pragma unroll
        for (int j = 0; j < 4; j++) acc[nt][j] = 0.f;

    auto fill = [&](int kt, int buf) {
        uint32_t st = sb + buf * TSTAGE;
        if (MODE == 0) {
            #pragma unroll
            for (int gq = 0; gq < 4; gq++) {
                int g = tid + gq * 256;
                int sel = g >> 9;
                int r = (g >> 3) & 63, seg = g & 7;
                const __nv_bfloat16* srcp = (sel ? al : ah) + (size_t)(m0 + r) * lda + (kt << 6) + (seg << 3);
                cp16(st + sel * TS_A + r * LDS_AB + seg * 16, srcp);
            }
        } else {
            char* stc = smem + buf * TSTAGE;
            #pragma unroll
            for (int gq = 0; gq < 2; gq++) {
                int g = tid + gq * 256;
                int row = g >> 3, c8 = g & 7;
                int m = m0 + row;
                int kg = (kt << 6) + (c8 << 3);
                float4 f0, f1;
                float cf;
                if (MODE == 1) {
                    int e = kg / KP_ZC, i = kg - e * KP_ZC;
                    cf = coeff[m * E_ + e];
                    f0 = *(const float4*)(src + (size_t)m * KP_ZC + i);
                    f1 = *(const float4*)(src + (size_t)m * KP_ZC + i + 4);
                } else {
                    int e = kg / IN1_, i = kg - e * IN1_;
                    cf = coeff[m * E_ + e];
                    if (i < L_) {
                        f0 = *(const float4*)(z + (size_t)m * L_ + i);
                        f1 = *(const float4*)(z + (size_t)m * L_ + i + 4);
                    } else {
                        f0 = *(const float4*)(src + (size_t)m * H_ + (i - L_));
                        f1 = *(const float4*)(src + (size_t)m * H_ + (i - L_) + 4);
                    }
                }
                float v[8] = { cf * f0.x, cf * f0.y, cf * f0.z, cf * f0.w,
                               cf * f1.x, cf * f1.y, cf * f1.z, cf * f1.w };
                union { __nv_bfloat16 b[8]; uint4 u; } hv, lv;
                #pragma unroll
                for (int j = 0; j < 8; j++) split_bf16(v[j], hv.b[j], lv.b[j]);
                *(uint4*)(stc + row * LDS_AB + c8 * 16) = hv.u;
                *(uint4*)(stc + TS_A + row * LDS_AB + c8 * 16) = lv.u;
            }
        }
        const __nv_bfloat16* th = wth + ((size_t)(ntile * KT + kt) << 12);
        const __nv_bfloat16* tl = wtl + ((size_t)(ntile * KT + kt) << 12);
        #pragma unroll
        for (int gq = 0; gq < 2; gq++) {
            int g = tid + gq * 256;
            int n = g >> 3, seg = g & 7;
            cp16(st + 2 * TS_A + n * LDS_AB + seg * 16, th + n * 64 + seg * 8);
            cp16(st + 2 * TS_A + TS_B + n * LDS_AB + seg * 16, tl + n * 64 + seg * 8);
        }
    };

    fill(kt0, 0);
    CP_COMMIT();
    CP_WAIT0();
    __syncthreads();

    for (int t = 0; t < ktn; t++) {
        int buf = t & 1;
        bool more = (t + 1) < ktn;
        if (more) {
            fill(kt0 + t + 1, buf ^ 1);
            CP_COMMIT();
        }

        uint32_t sA = sb + buf * TSTAGE;
        uint32_t sB = sA + 2 * TS_A;
        int arow = wm * 16 + (lane & 15);
        int bn = wn * 32 + ((lane >> 4) << 3) + (lane & 7);
        int bkl = ((lane >> 3) & 1) << 3;
        #pragma unroll
        for (int ks = 0; ks < 4; ks++) {
            uint32_t ahf[4], alf[4];
            uint32_t bh0[4], bh1[4], bl0[4], bl1[4];
            uint32_t aAdr = sA + arow * LDS_AB + (ks * 16 + (lane >> 4) * 8) * 2;
            ldsm_x4(ahf, aAdr);
            ldsm_x4(alf, aAdr + TS_A);
            uint32_t bAdr = sB + bn * LDS_AB + (ks * 16 + bkl) * 2;
            ldsm_x4(bh0, bAdr);
            ldsm_x4(bh1, bAdr + 16 * LDS_AB);
            ldsm_x4(bl0, bAdr + TS_B);
            ldsm_x4(bl1, bAdr + TS_B + 16 * LDS_AB);

            mma16816(acc[0], ahf, bh0);     mma16816(acc[1], ahf, bh0 + 2);
            mma16816(acc[2], ahf, bh1);     mma16816(acc[3], ahf, bh1 + 2);

            mma16816(acc[0], ahf, bl0);     mma16816(acc[1], ahf, bl0 + 2);
            mma16816(acc[2], ahf, bl1);     mma16816(acc[3], ahf, bl1 + 2);

            mma16816(acc[0], alf, bh0);     mma16816(acc[1], alf, bh0 + 2);
            mma16816(acc[2], alf, bh1);     mma16816(acc[3], alf, bh1 + 2);
        }
        if (more) CP_WAIT0();
        __syncthreads();
    }

    #pragma unroll
    for (int nt = 0; nt < 4; nt++) {
        int m = m0 + wm * 16 + (lane >> 2);
        int n = n0 + wn * 32 + nt * 8 + ((lane & 3) << 1);
        *(float2*)(Cp + (size_t)m * ldc + n) = make_float2(acc[nt][0], acc[nt][1]);
        *(float2*)(Cp + (size_t)(m + 8) * ldc + n) = make_float2(acc[nt][2], acc[nt][3]);
    }
}

// ---------------- split-K combines ----------------
// scalar combine (used for ragged final N=267)
__global__ void combine(const float* __restrict__ part, int S, int ldp,
                        float* __restrict__ C, int ldc, int Nout,
                        const float* __restrict__ bias,
                        const float* __restrict__ coeff,
                        const float* __restrict__ ebias, int ebld,
                        int act)
{
    int idx = blockIdx.x * blockDim.x + threadIdx.x;
    if (idx >= B_ * Nout) return;
    int m = idx / Nout, n = idx % Nout;
    float v = 0.f;
    for (int s = 0; s < S; s++) v += part[(size_t)s * B_ * ldp + (size_t)m * ldp + n];
    if (bias) v += bias[n];
    if (ebias) {
        const float* cf = coeff + m * E_;
        float bm = 0.f;
        #pragma unroll
        for (int e = 0; e < E_; e++) bm = fmaf(cf[e], ebias[e * ebld + n], bm);
        v += bm;
    }
    if (act) v = elu1(v);
    C[(size_t)m * ldc + n] = v;
}

// float4 combine (Nout % 4 == 0, ldc == ldp == Nout)
__global__ void combine4(const float* __restrict__ part, int S, int Nout,
                         float* __restrict__ C,
                         const float* __restrict__ bias,
                         const float* __restrict__ coeff,
                         const float* __restrict__ ebias, int ebld,
                         int act)
{
    int idx = blockIdx.x * blockDim.x + threadIdx.x;
    int q = Nout >> 2;
    if (idx >= B_ * q) return;
    int m = idx / q, n = (idx % q) << 2;
    float4 v = make_float4(0.f, 0.f, 0.f, 0.f);
    for (int s = 0; s < S; s++) {
        float4 p = *(const float4*)(part + (size_t)s * B_ * Nout + (size_t)m * Nout + n);
        v.x += p.x; v.y += p.y; v.z += p.z; v.w += p.w;
    }
    if (bias) {
        float4 bv = *(const float4*)(bias + n);
        v.x += bv.x; v.y += bv.y; v.z += bv.z; v.w += bv.w;
    }
    if (ebias) {
        const float* cf = coeff + m * E_;
        #pragma unroll
        for (int e = 0; e < E_; e++) {
            float4 eb = *(const float4*)(ebias + (size_t)e * ebld + n);
            float ce = cf[e];
            v.x = fmaf(ce, eb.x, v.x);
            v.y = fmaf(ce, eb.y, v.y);
            v.z = fmaf(ce, eb.z, v.z);
            v.w = fmaf(ce, eb.w, v.w);
        }
    }
    if (act) { v.x = elu1(v.x); v.y = elu1(v.y); v.z = elu1(v.z); v.w = elu1(v.w); }
    *(float4*)(C + (size_t)m * Nout + n) = v;
}

// float4 combine into encB bf16 hi/lo h-slot
__global__ void combine_h(const float* __restrict__ part, int S,
                          __nv_bfloat16* __restrict__ Ch, __nv_bfloat16* __restrict__ Cl,
                          const float* __restrict__ bias)
{
    int idx = blockIdx.x * blockDim.x + threadIdx.x;
    if (idx >= B_ * (H_ / 4)) return;
    int m = idx / (H_ / 4), n = (idx % (H_ / 4)) << 2;
    float4 v = *(const float4*)(bias + n);
    for (int s = 0; s < S; s++) {
        float4 p = *(const float4*)(part + (size_t)s * B_ * 256 + (size_t)m * 256 + n);
        v.x += p.x; v.y += p.y; v.z += p.z; v.w += p.w;
    }
    v.x = elu1(v.x); v.y = elu1(v.y); v.z = elu1(v.z); v.w = elu1(v.w);
    float vv[4] = { v.x, v.y, v.z, v.w };
    size_t dst = (size_t)m * KP_ENC + 267 + n;
    #pragma unroll
    for (int j = 0; j < 4; j++) {
        __nv_bfloat16 h, l;
        split_bf16(vv[j], h, l);
        Ch[dst + j] = h;
        Cl[dst + j] = l;
    }
}

// ---------------- host launch ----------------
static inline void* sym(const void* s) { void* p = nullptr; cudaGetSymbolAddress(&p, s); return p; }

extern "C" void kernel_launch(void* const* d_in, const int* in_sizes, int n_in,
                              void* d_out, int out_size) {
    (void)in_sizes; (void)n_in; (void)out_size;
    const float* x     = (const float*)d_in[0];
    const float* c     = (const float*)d_in[1];
    const float* fc1_w = (const float*)d_in[2];
    const float* fc1_b = (const float*)d_in[3];
    const float* fc2_w = (const float*)d_in[4];
    const float* fc2_b = (const float*)d_in[5];
    const float* mu_w  = (const float*)d_in[6];
    const float* mu_b  = (const float*)d_in[7];
    const float* lv_w  = (const float*)d_in[8];
    const float* lv_b  = (const float*)d_in[9];
    const float* g0_w  = (const float*)d_in[10];
    const float* g0_b  = (const float*)d_in[11];
    const float* g1_w  = (const float*)d_in[12];
    const float* g1_b  = (const float*)d_in[13];
    const float* g2_w  = (const float*)d_in[14];
    const float* g2_b  = (const float*)d_in[15];
    const float* w0    = (const float*)d_in[16];
    const float* b0    = (const float*)d_in[17];
    const float* w1    = (const float*)d_in[18];
    const float* b1    = (const float*)d_in[19];
    const float* w2    = (const float*)d_in[20];
    const float* b2    = (const float*)d_in[21];

    float* out       = (float*)d_out;
    float* out_layer = out;
    float* out_mu    = out + B_ * F_;
    float* out_lv    = out + B_ * F_ + B_ * L_;

    __nv_bfloat16* eAh = (__nv_bfloat16*)sym(g_encAh);
    __nv_bfloat16* eAl = (__nv_bfloat16*)sym(g_encAl);
    __nv_bfloat16* eBh = (__nv_bfloat16*)sym(g_encBh);
    __nv_bfloat16* eBl = (__nv_bfloat16*)sym(g_encBl);
    __nv_bfloat16* zch = (__nv_bfloat16*)sym(g_zch);
    __nv_bfloat16* zcl = (__nv_bfloat16*)sym(g_zcl);
    float* z     = (float*)sym(g_z);
    float* zc    = (float*)sym(g_zc);
    float* g0o   = (float*)sym(g_g0o);
    float* coef  = (float*)sym(g_coef);
    float* d0    = (float*)sym(g_d0);
    float* d1    = (float*)sym(g_d1);
    float* part  = (float*)sym(g_part);
    float* bmulv = (float*)sym(g_bmulv);
    float* wg1   = (float*)sym(g_wg1);
    __nv_bfloat16* we1h = (__nv_bfloat16*)sym(g_wte1h);
    __nv_bfloat16* we1l = (__nv_bfloat16*)sym(g_wte1l);
    __nv_bfloat16* we2h = (__nv_bfloat16*)sym(g_wte2h);
    __nv_bfloat16* we2l = (__nv_bfloat16*)sym(g_wte2l);
    __nv_bfloat16* wmvh = (__nv_bfloat16*)sym(g_wtmvh);
    __nv_bfloat16* wmvl = (__nv_bfloat16*)sym(g_wtmvl);
    __nv_bfloat16* wg0h = (__nv_bfloat16*)sym(g_wg0th);
    __nv_bfloat16* wg0l = (__nv_bfloat16*)sym(g_wg0tl);
    __nv_bfloat16* wt0h = (__nv_bfloat16*)sym(g_wt0h);
    __nv_bfloat16* wt0l = (__nv_bfloat16*)sym(g_wt0l);
    __nv_bfloat16* wt1h = (__nv_bfloat16*)sym(g_wt1h);
    __nv_bfloat16* wt1l = (__nv_bfloat16*)sym(g_wt1l);
    __nv_bfloat16* wt2h = (__nv_bfloat16*)sym(g_wt2h);
    __nv_bfloat16* wt2l = (__nv_bfloat16*)sym(g_wt2l);

    cudaFuncSetAttribute(tgemm<0>, cudaFuncAttributeMaxDynamicSharedMemorySize, TSM_TOTAL);
    cudaFuncSetAttribute(tgemm<1>, cudaFuncAttributeMaxDynamicSharedMemorySize, TSM_TOTAL);
    cudaFuncSetAttribute(tgemm<2>, cudaFuncAttributeMaxDynamicSharedMemorySize, TSM_TOTAL);
    cudaFuncSetAttribute(tgemm<0>, cudaFuncAttributePreferredSharedMemoryCarveout, 100);
    cudaFuncSetAttribute(tgemm<1>, cudaFuncAttributePreferredSharedMemoryCarveout, 100);
    cudaFuncSetAttribute(tgemm<2>, cudaFuncAttributePreferredSharedMemoryCarveout, 100);

    const int T = 256;
    auto gr = [](int n) { return (n + 255) / 256; };

    pack_all<<<gr(PKTOT), T>>>(mu_b, lv_b, g1_w, bmulv, wg1);
    tpack<<<gr(WTE1_SZ + WTE2_SZ + WTMV_SZ + WG0T_SZ + WT0_SZ + WT1_SZ + WT2_SZ), T>>>(
        fc1_w, fc2_w, mu_w, lv_w, g0_w, w0, w1, w2,
        we1h, we1l, we2h, we2l, wmvh, wmvl, wg0h, wg0l,
        wt0h, wt0l, wt1h, wt1l, wt2h, wt2l);
    prep_inputs<<<gr(PR0 + PR1 + PR2 + PR3), T>>>(x, c, eAh, eAl, eBh, eBl, zc, zch, zcl);

    // ---- encoder fc1 (split-K 5, ktPer 2, grid 640) ----
    tgemm<0><<<dim3(4, 32, 5), T, TSM_TOTAL>>>(nullptr, KP_ENC, eAh, eAl, nullptr, nullptr,
                                               we1h, we1l, part, 256, (long)B_ * 256, KT_ENC, 2, KT_ENC);
    combine_h<<<gr(B_ * (H_ / 4)), T>>>(part, 5, eBh, eBl, fc1_b);

    // ---- encoder fc2 (split-K 5) ----
    tgemm<0><<<dim3(4, 32, 5), T, TSM_TOTAL>>>(nullptr, KP_ENC, eBh, eBl, nullptr, nullptr,
                                               we2h, we2l, part, 256, (long)B_ * 256, KT_ENC, 2, KT_ENC);
    combine_h<<<gr(B_ * (H_ / 4)), T>>>(part, 5, eBh, eBl, fc2_b);

    // ---- mu/lv (split-K 9) + fused z sampling ----
    tgemm<0><<<dim3(1, 32, 9), T, TSM_TOTAL>>>(nullptr, KP_ENC, eBh, eBl, nullptr, nullptr,
                                               wmvh, wmvl, part, 64, (long)B_ * 64, KT_ENC, 1, KT_ENC);
    combine_zeps<<<gr(B_ * L_), T>>>(part, 9, bmulv, z, zc, zch, zcl, out_mu, out_lv);

    // ---- gate: g0 tensor (split-K 5) + fused g1/g2/softmax ----
    tgemm<0><<<dim3(1, 32, 5), T, TSM_TOTAL>>>(nullptr, KP_G0, zch, zcl, nullptr, nullptr,
                                               wg0h, wg0l, part, 64, (long)B_ * 64, KT_G0, 1, KT_G0);
    combine4<<<gr(B_ * (G_ / 4)), T>>>(part, 5, 64, g0o, g0_b, nullptr, nullptr, 0, 1);
    gate12<<<gr(B_ * 32), T>>>(g0o, wg1, g1_b, g2_w, g2_b, coef);

    // ---- decoder: split-K 8 ----
    tgemm<1><<<dim3(NT_L01, 32, 8), T, TSM_TOTAL>>>(zc, 0, nullptr, nullptr, nullptr, coef,
                                                    wt0h, wt0l, part, 256, (long)B_ * 256, KT_L0, 5, KT_L0);
    combine4<<<gr(B_ * (H_ / 4)), T>>>(part, 8, 256, d0, nullptr, coef, b0, 256, 1);

    tgemm<2><<<dim3(NT_L01, 32, 8), T, TSM_TOTAL>>>(d0, 0, nullptr, nullptr, z, coef,
                                                    wt1h, wt1l, part, 256, (long)B_ * 256, KT_L12, 5, KT_L12);
    combine4<<<gr(B_ * (H_ / 4)), T>>>(part, 8, 256, d1, nullptr, coef, b1, 256, 1);

    tgemm<2><<<dim3(NT_L2, 32, 8), T, TSM_TOTAL>>>(d1, 0, nullptr, nullptr, z, coef,
                                                   wt2h, wt2l, part, NP_W2, (long)B_ * NP_W2, KT_L12, 5, KT_L12);
    combine<<<gr(B_ * 267), T>>>(part, 8, NP_W2, out_layer, 267, 267, nullptr, coef, b2, 267, 0);
}